// round 11
// baseline (speedup 1.0000x reference)
#include <cuda_runtime.h>
#include <cuda_bf16.h>
#include <cstdint>

#define BB 4
#define NN 8192
#define KK 16
#define CC 128
#define TT 3
#define BN_ (BB*NN)          // 32768 points
#define CE 131               // 3 + C
#define ES 132               // padded A row stride (floats) -> conflict-free frags
#define NT2 (BN_/4)          // 8192 edge tiles (4 points x 16 nbrs = 64 rows)

// ---------------- device scratch ----------------
__device__ __align__(16) float g_featA[BN_*CC];
__device__ __align__(16) float g_featB[BN_*CC];
__device__ __align__(16) float g_featTF[BN_*CC];  // tf32-rounded mirror of current features
__device__ __align__(16) float g_agg[BN_*CC];
__device__ float  g_center[BN_*3];
__device__ float4 g_posw[TT*CC];        // {w0,w1,w2,b1} per edge output n
// packed tf32 weight fragments: idx y in [0,4096): lid=y&31, nt=(y>>5)&15, p2=y>>9
// float4 = {W[n][16p2+q], W[n][16p2+q+4], W[n][16p2+q+8], W[n][16p2+q+12]}, n=nt*8+(lid>>2), q=lid&3
__device__ float4 g_pkE1[TT][4096];
__device__ float4 g_pkE2[TT][4096];
__device__ float4 g_pkU1[TT][2][4096];
__device__ float4 g_pkU2[TT][4096];
__device__ float4 g_pkO1[4096];
__device__ float4 g_pkO2[256];          // n8 fragment (rows 3..7 zero)

// ---------------- helpers ----------------
__device__ __forceinline__ float f2tf(float x) {
    uint32_t u; asm("cvt.rna.tf32.f32 %0, %1;" : "=r"(u) : "f"(x));
    return __uint_as_float(u);
}
__device__ __forceinline__ float4 f2tf4(float4 v) {
    v.x = f2tf(v.x); v.y = f2tf(v.y); v.z = f2tf(v.z); v.w = f2tf(v.w);
    return v;
}
__device__ __forceinline__ uint32_t s2u(const void* p) {
    uint32_t a;
    asm("{ .reg .u64 t; cvta.to.shared.u64 t, %1; cvt.u32.u64 %0, t; }" : "=r"(a) : "l"(p));
    return a;
}
__device__ __forceinline__ void cpasync16(uint32_t dst, const void* src) {
    asm volatile("cp.async.cg.shared.global [%0], [%1], 16;" :: "r"(dst), "l"(src));
}
#define CP_COMMIT() asm volatile("cp.async.commit_group;" ::: "memory")
#define CP_WAIT0()  asm volatile("cp.async.wait_group 0;" ::: "memory")

__device__ __forceinline__ void mma8(float* c, uint32_t a0, uint32_t a1,
                                     uint32_t a2, uint32_t a3,
                                     uint32_t b0, uint32_t b1) {
    asm volatile(
        "mma.sync.aligned.m16n8k8.row.col.f32.tf32.tf32.f32 "
        "{%0,%1,%2,%3}, {%4,%5,%6,%7}, {%8,%9}, {%0,%1,%2,%3};"
        : "+f"(c[0]), "+f"(c[1]), "+f"(c[2]), "+f"(c[3])
        : "r"(a0), "r"(a1), "r"(a2), "r"(a3), "r"(b0), "r"(b1));
}
__device__ __forceinline__ uint32_t ldu(const float* p) { return __float_as_uint(*p); }

// full warp GEMM: 16 rows x 128 N over K=128 (offset/upd).
__device__ __forceinline__ void wgemm(float acc[16][4], const float* __restrict__ abase,
                                      const float4* __restrict__ pb,
                                      int mrow0, int g, int q, int lid) {
    const float* ar0 = abase + (mrow0 + g) * ES + q;
    const float* ar1 = ar0 + 8 * ES;
    #pragma unroll
    for (int p2 = 0; p2 < 8; p2++) {
        int k0 = p2 * 16;
        uint32_t aE0 = ldu(ar0 + k0),      aE2 = ldu(ar0 + k0 + 4);
        uint32_t aE1 = ldu(ar1 + k0),      aE3 = ldu(ar1 + k0 + 4);
        uint32_t aO0 = ldu(ar0 + k0 + 8),  aO2 = ldu(ar0 + k0 + 12);
        uint32_t aO1 = ldu(ar1 + k0 + 8),  aO3 = ldu(ar1 + k0 + 12);
        const float4* pbl = pb + p2 * 512 + lid;
        #pragma unroll
        for (int nt = 0; nt < 16; nt++) {
            float4 w = pbl[nt * 32];
            mma8(acc[nt], aE0, aE1, aE2, aE3, __float_as_uint(w.x), __float_as_uint(w.y));
            mma8(acc[nt], aO0, aO1, aO2, aO3, __float_as_uint(w.z), __float_as_uint(w.w));
        }
    }
}

// edge warp GEMM: 32 rows (2x16 groups at row0) x 16 N (sixteenth ns) over K=128.
__device__ __forceinline__ void wgemm64(float acc[2][2][4], const float* __restrict__ abase,
                                        const float4* __restrict__ pb,
                                        int row0, int g, int q, int lid, int ns) {
    const float* a0 = abase + (row0 + g) * ES + q;
    #pragma unroll
    for (int p2 = 0; p2 < 8; p2++) {
        int k0 = p2 * 16;
        uint32_t E0[2], E1[2], E2[2], E3[2], O0[2], O1[2], O2[2], O3[2];
        #pragma unroll
        for (int mg = 0; mg < 2; mg++) {
            const float* r0p = a0 + mg * 16 * ES + k0;
            const float* r1p = r0p + 8 * ES;
            E0[mg] = ldu(r0p);      E2[mg] = ldu(r0p + 4);
            E1[mg] = ldu(r1p);      E3[mg] = ldu(r1p + 4);
            O0[mg] = ldu(r0p + 8);  O2[mg] = ldu(r0p + 12);
            O1[mg] = ldu(r1p + 8);  O3[mg] = ldu(r1p + 12);
        }
        const float4* pbl = pb + p2 * 512 + ns * 64 + lid;
        #pragma unroll
        for (int ntl = 0; ntl < 2; ntl++) {
            float4 w = pbl[ntl * 32];
            uint32_t b0 = __float_as_uint(w.x), b1 = __float_as_uint(w.y);
            uint32_t b2 = __float_as_uint(w.z), b3 = __float_as_uint(w.w);
            #pragma unroll
            for (int mg = 0; mg < 2; mg++) {
                mma8(acc[mg][ntl], E0[mg], E1[mg], E2[mg], E3[mg], b0, b1);
                mma8(acc[mg][ntl], O0[mg], O1[mg], O2[mg], O3[mg], b2, b3);
            }
        }
    }
}

// ---------------- prep ----------------
__global__ void prep_kernel(const float* __restrict__ features,
                            const float* __restrict__ off_W1, const float* __restrict__ off_W2,
                            const float* __restrict__ edge_W1, const float* __restrict__ edge_b1,
                            const float* __restrict__ edge_W2,
                            const float* __restrict__ upd_W1, const float* __restrict__ upd_W2) {
    int i0 = blockIdx.x * blockDim.x + threadIdx.x, st = gridDim.x * blockDim.x;
    for (int x = i0; x < BN_ * CC; x += st) g_featTF[x] = f2tf(features[x]);
    for (int x = i0; x < TT * 4096; x += st) {
        int t = x >> 12, y = x & 4095;
        int lid = y & 31, nt = (y >> 5) & 15, p2 = y >> 9;
        int n = nt * 8 + (lid >> 2), q = lid & 3, k = p2 * 16 + q;
        const float* s1 = edge_W1 + ((size_t)t * CC + n) * CE + 3;
        g_pkE1[t][y] = make_float4(f2tf(s1[k]), f2tf(s1[k+4]), f2tf(s1[k+8]), f2tf(s1[k+12]));
        const float* s2 = edge_W2 + ((size_t)t * CC + n) * CC;
        g_pkE2[t][y] = make_float4(f2tf(s2[k]), f2tf(s2[k+4]), f2tf(s2[k+8]), f2tf(s2[k+12]));
        const float* u1 = upd_W1 + ((size_t)t * CC + n) * 2 * CC;
        g_pkU1[t][0][y] = make_float4(f2tf(u1[k]), f2tf(u1[k+4]), f2tf(u1[k+8]), f2tf(u1[k+12]));
        const float* u1b = u1 + CC;
        g_pkU1[t][1][y] = make_float4(f2tf(u1b[k]), f2tf(u1b[k+4]), f2tf(u1b[k+8]), f2tf(u1b[k+12]));
        const float* u2 = upd_W2 + ((size_t)t * CC + n) * CC;
        g_pkU2[t][y] = make_float4(f2tf(u2[k]), f2tf(u2[k+4]), f2tf(u2[k+8]), f2tf(u2[k+12]));
    }
    for (int x = i0; x < 4096; x += st) {
        int lid = x & 31, nt = (x >> 5) & 15, p2 = x >> 9;
        int n = nt * 8 + (lid >> 2), q = lid & 3, k = p2 * 16 + q;
        const float* s = off_W1 + (size_t)n * CC;
        g_pkO1[x] = make_float4(f2tf(s[k]), f2tf(s[k+4]), f2tf(s[k+8]), f2tf(s[k+12]));
    }
    for (int x = i0; x < 256; x += st) {
        int lid = x & 31, p2 = x >> 5;
        int n = lid >> 2, q = lid & 3, k = p2 * 16 + q;
        if (n < 3) {
            const float* s = off_W2 + (size_t)n * CC;
            g_pkO2[x] = make_float4(f2tf(s[k]), f2tf(s[k+4]), f2tf(s[k+8]), f2tf(s[k+12]));
        } else {
            g_pkO2[x] = make_float4(0.f, 0.f, 0.f, 0.f);
        }
    }
    for (int x = i0; x < TT * CC; x += st) {
        int t = x >> 7, n = x & 127;
        const float* w = edge_W1 + ((size_t)t * CC + n) * CE;
        g_posw[x] = make_float4(w[0], w[1], w[2], edge_b1[t * CC + n]);
    }
}

// ---------------- offset kernel: tensor-core, 256 points/CTA ----------------
#define OO_F    0
#define OO_W1   33792
#define OO_W2   50176
#define OO_B1   51200
#define OO_B2   51328
#define O_SMEMF 51336
#define O_SMEM  (O_SMEMF*4)

__global__ void __launch_bounds__(512) offset_kernel(
    const float* __restrict__ feat, const float* __restrict__ xyz,
    const float* __restrict__ b1, const float* __restrict__ b2) {
    extern __shared__ __align__(16) float sm[];
    float*  fs  = sm + OO_F;
    float4* w1s = (float4*)(sm + OO_W1);
    float4* w2s = (float4*)(sm + OO_W2);
    float*  b1s = sm + OO_B1;
    float*  b2s = sm + OO_B2;

    const int tid = threadIdx.x, wid = tid >> 5, lid = tid & 31;
    const int g = lid >> 2, q = lid & 3;
    const int mrow0 = wid * 16;
    int p0 = blockIdx.x * 256;

    for (int i = tid; i < 4096; i += 512) w1s[i] = g_pkO1[i];
    if (tid < 256) w2s[tid] = g_pkO2[tid];
    if (tid < CC) b1s[tid] = b1[tid];
    if (tid < 3) b2s[tid] = b2[tid];
    for (int r = wid; r < 256; r += 16) {
        const float4* src = (const float4*)(feat + (size_t)(p0 + r) * CC);
        *(float4*)&fs[r * ES + lid * 4] = f2tf4(src[lid]);
    }
    __syncthreads();

    float acc[16][4];
    #pragma unroll
    for (int nt = 0; nt < 16; nt++)
        acc[nt][0] = acc[nt][1] = acc[nt][2] = acc[nt][3] = 0.f;
    wgemm(acc, fs, w1s, mrow0, g, q, lid);

    {
        int r0 = mrow0 + g, r1 = r0 + 8;
        #pragma unroll
        for (int nt = 0; nt < 16; nt++) {
            int n = nt * 8 + q * 2;
            float c0 = b1s[n], c1 = b1s[n + 1];
            *(float2*)&fs[r0 * ES + n] = make_float2(f2tf(fmaxf(acc[nt][0] + c0, 0.f)),
                                                     f2tf(fmaxf(acc[nt][1] + c1, 0.f)));
            *(float2*)&fs[r1 * ES + n] = make_float2(f2tf(fmaxf(acc[nt][2] + c0, 0.f)),
                                                     f2tf(fmaxf(acc[nt][3] + c1, 0.f)));
        }
    }

    float a2[4] = {0.f, 0.f, 0.f, 0.f};
    {
        const float* ar0 = fs + (mrow0 + g) * ES + q;
        const float* ar1 = ar0 + 8 * ES;
        #pragma unroll
        for (int p2 = 0; p2 < 8; p2++) {
            int k0 = p2 * 16;
            uint32_t aE0 = ldu(ar0 + k0),     aE2 = ldu(ar0 + k0 + 4);
            uint32_t aE1 = ldu(ar1 + k0),     aE3 = ldu(ar1 + k0 + 4);
            uint32_t aO0 = ldu(ar0 + k0 + 8), aO2 = ldu(ar0 + k0 + 12);
            uint32_t aO1 = ldu(ar1 + k0 + 8), aO3 = ldu(ar1 + k0 + 12);
            float4 w = w2s[p2 * 32 + lid];
            mma8(a2, aE0, aE1, aE2, aE3, __float_as_uint(w.x), __float_as_uint(w.y));
            mma8(a2, aO0, aO1, aO2, aO3, __float_as_uint(w.z), __float_as_uint(w.w));
        }
    }
    {
        int r0 = p0 + mrow0 + g, r1 = r0 + 8;
        if (q == 0) {
            g_center[r0*3 + 0] = xyz[r0*3 + 0] + a2[0] + b2s[0];
            g_center[r0*3 + 1] = xyz[r0*3 + 1] + a2[1] + b2s[1];
            g_center[r1*3 + 0] = xyz[r1*3 + 0] + a2[2] + b2s[0];
            g_center[r1*3 + 1] = xyz[r1*3 + 1] + a2[3] + b2s[1];
        } else if (q == 1) {
            g_center[r0*3 + 2] = xyz[r0*3 + 2] + a2[0] + b2s[2];
            g_center[r1*3 + 2] = xyz[r1*3 + 2] + a2[2] + b2s[2];
        }
    }
}

// ---------------- edge kernel: persistent, double-buffered 64-row tiles ----------------
// smem floats: es[2][64*ES]=16896, w1 16384, w2 16384, posw 512, eb2 128
#define EO_ES   0
#define EO_W1   16896
#define EO_W2   33280
#define EO_PW   49664
#define EO_EB2  50176
#define E_SMEMF 50304
#define E_SMEM  (E_SMEMF*4)
#define EBUF    (64*ES)

__global__ void __launch_bounds__(512, 1) edge_kernel(
    const float* __restrict__ xyz, const int* __restrict__ knn,
    const float* __restrict__ eb2, int t) {
    extern __shared__ __align__(16) float sm[];
    float*  es0  = sm + EO_ES;
    float4* w1s  = (float4*)(sm + EO_W1);
    float4* w2s  = (float4*)(sm + EO_W2);
    float4* posw = (float4*)(sm + EO_PW);
    float*  eb2s = sm + EO_EB2;

    const int tid = threadIdx.x, wid = tid >> 5, lid = tid & 31;
    const int g = lid >> 2, q = lid & 3;
    const int rw = wid & 1;          // 32-row group (= 2 points)
    const int ns = wid >> 1;         // N sixteenth (16 cols)
    const int row0 = rw * 32;
    const int grow = tid >> 3;       // gather row (0..63)
    const int seg  = tid & 7;        // 64B segment within 512B row
    const uint32_t es_base = s2u(es0);

    for (int i = tid; i < 4096; i += 512) { w1s[i] = g_pkE1[t][i]; w2s[i] = g_pkE2[t][i]; }
    if (tid < CC) { posw[tid] = g_posw[t * CC + tid]; eb2s[tid] = eb2[t * CC + tid]; }

    int tt = blockIdx.x;
    int cur = 0;
    // prologue: prefetch first tile into buf 0
    if (tt < NT2) {
        int p0 = tt * 4, base = p0 & ~(NN - 1);
        int idx = __ldg(&knn[(size_t)p0 * KK + grow]);
        const float* src = g_featTF + (size_t)(base + idx) * CC + seg * 16;
        uint32_t dst = es_base + (uint32_t)(grow * ES + seg * 16) * 4;
        #pragma unroll
        for (int j = 0; j < 4; j++) cpasync16(dst + j * 16, src + j * 4);
    }
    CP_COMMIT();

    for (; tt < NT2; tt += gridDim.x) {
        int p0 = tt * 4, base = p0 & ~(NN - 1);
        CP_WAIT0();          // current tile's gather arrived
        __syncthreads();     // all warps past previous tile's compute

        // prefetch NEXT tile into the other buffer (overlaps with this tile's compute)
        int nxt = tt + (int)gridDim.x;
        if (nxt < NT2) {
            int np0 = nxt * 4, nbase = np0 & ~(NN - 1);
            int idx = __ldg(&knn[(size_t)np0 * KK + grow]);
            const float* src = g_featTF + (size_t)(nbase + idx) * CC + seg * 16;
            uint32_t dst = es_base + (uint32_t)((cur ^ 1) * EBUF + grow * ES + seg * 16) * 4;
            #pragma unroll
            for (int j = 0; j < 4; j++) cpasync16(dst + j * 16, src + j * 4);
        }
        CP_COMMIT();

        float* es = es0 + cur * EBUF;

        // issue relpos raw loads now; consumed in epilogue1 (latency hidden by layer1)
        float xr[2][2][3], cx[2][3];
        #pragma unroll
        for (int mg = 0; mg < 2; mg++) {
            int p = p0 + rw * 2 + mg;
            cx[mg][0] = __ldg(&g_center[p*3+0]);
            cx[mg][1] = __ldg(&g_center[p*3+1]);
            cx[mg][2] = __ldg(&g_center[p*3+2]);
            #pragma unroll
            for (int h = 0; h < 2; h++) {
                int row = row0 + mg * 16 + g + h * 8;
                int nb = base + __ldg(&knn[(size_t)p0 * KK + row]);
                xr[mg][h][0] = __ldg(&xyz[nb*3+0]);
                xr[mg][h][1] = __ldg(&xyz[nb*3+1]);
                xr[mg][h][2] = __ldg(&xyz[nb*3+2]);
            }
        }

        // layer 1 (feat part)
        float acc[2][2][4];
        #pragma unroll
        for (int mg = 0; mg < 2; mg++)
            #pragma unroll
            for (int ntl = 0; ntl < 2; ntl++)
                acc[mg][ntl][0] = acc[mg][ntl][1] = acc[mg][ntl][2] = acc[mg][ntl][3] = 0.f;
        wgemm64(acc, es, w1s, row0, g, q, lid, ns);

        // epilogue1: + rel_pos·W + b1 (exact fp32), ReLU, tf32 -> own rows/cols
        #pragma unroll
        for (int mg = 0; mg < 2; mg++) {
            int r0 = row0 + mg * 16 + g, r1 = r0 + 8;
            float rx0 = xr[mg][0][0] - cx[mg][0], ry0 = xr[mg][0][1] - cx[mg][1], rz0 = xr[mg][0][2] - cx[mg][2];
            float rx1 = xr[mg][1][0] - cx[mg][0], ry1 = xr[mg][1][1] - cx[mg][1], rz1 = xr[mg][1][2] - cx[mg][2];
            #pragma unroll
            for (int ntl = 0; ntl < 2; ntl++) {
                int n = ns * 16 + ntl * 8 + q * 2;
                float4 pwa = posw[n], pwb = posw[n + 1];
                float pa0 = rx0*pwa.x + ry0*pwa.y + rz0*pwa.z + pwa.w;
                float pb0 = rx0*pwb.x + ry0*pwb.y + rz0*pwb.z + pwb.w;
                float pa1 = rx1*pwa.x + ry1*pwa.y + rz1*pwa.z + pwa.w;
                float pb1 = rx1*pwb.x + ry1*pwb.y + rz1*pwb.z + pwb.w;
                *(float2*)&es[r0 * ES + n] = make_float2(f2tf(fmaxf(acc[mg][ntl][0] + pa0, 0.f)),
                                                         f2tf(fmaxf(acc[mg][ntl][1] + pb0, 0.f)));
                *(float2*)&es[r1 * ES + n] = make_float2(f2tf(fmaxf(acc[mg][ntl][2] + pa1, 0.f)),
                                                         f2tf(fmaxf(acc[mg][ntl][3] + pb1, 0.f)));
            }
        }
        __syncthreads();

        // layer 2
        #pragma unroll
        for (int mg = 0; mg < 2; mg++)
            #pragma unroll
            for (int ntl = 0; ntl < 2; ntl++)
                acc[mg][ntl][0] = acc[mg][ntl][1] = acc[mg][ntl][2] = acc[mg][ntl][3] = 0.f;
        wgemm64(acc, es, w2s, row0, g, q, lid, ns);

        // epilogue2: per mg-group = one point's 16 neighbor rows -> max, +b2
        #pragma unroll
        for (int mg = 0; mg < 2; mg++) {
            int p = p0 + rw * 2 + mg;
            float* outp = g_agg + (size_t)p * CC;
            #pragma unroll
            for (int ntl = 0; ntl < 2; ntl++) {
                float m0 = fmaxf(acc[mg][ntl][0], acc[mg][ntl][2]);
                float m1 = fmaxf(acc[mg][ntl][1], acc[mg][ntl][3]);
                #pragma unroll
                for (int s = 4; s <= 16; s <<= 1) {
                    m0 = fmaxf(m0, __shfl_xor_sync(0xffffffffu, m0, s));
                    m1 = fmaxf(m1, __shfl_xor_sync(0xffffffffu, m1, s));
                }
                if (g == 0) {
                    int n = ns * 16 + ntl * 8 + q * 2;
                    *(float2*)&outp[n] = make_float2(m0 + eb2s[n], m1 + eb2s[n + 1]);
                }
            }
        }
        cur ^= 1;
    }
}

// ---------------- upd kernel: 512 threads, 256 points/CTA ----------------
#define UO_A    0
#define UO_W    33792
#define UO_B1   50176
#define UO_B2   50304
#define U_SMEMF 50432
#define U_SMEM  (U_SMEMF*4)

__global__ void __launch_bounds__(512) upd_kernel(
    const float* __restrict__ src, float* __restrict__ dst,
    const float* __restrict__ ub1, const float* __restrict__ ub2, int t) {
    extern __shared__ __align__(16) float sm[];
    float*  au   = sm + UO_A;
    float4* wbuf = (float4*)(sm + UO_W);
    float*  ub1s = sm + UO_B1;
    float*  ub2s = sm + UO_B2;

    const int tid = threadIdx.x, wid = tid >> 5, lid = tid & 31;
    const int g = lid >> 2, q = lid & 3;
    const int mrow0 = wid * 16;
    int p0 = blockIdx.x * 256;

    for (int r = wid; r < 256; r += 16) {
        const float4* a = (const float4*)(g_agg + (size_t)(p0 + r) * CC);
        *(float4*)&au[r * ES + lid * 4] = f2tf4(a[lid]);
    }
    for (int i = tid; i < 4096; i += 512) wbuf[i] = g_pkU1[t][0][i];
    if (tid < CC) { ub1s[tid] = ub1[t*CC + tid]; ub2s[tid] = ub2[t*CC + tid]; }
    __syncthreads();

    float acc[16][4];
    #pragma unroll
    for (int nt = 0; nt < 16; nt++)
        acc[nt][0] = acc[nt][1] = acc[nt][2] = acc[nt][3] = 0.f;
    wgemm(acc, au, wbuf, mrow0, g, q, lid);
    __syncthreads();

    for (int r = wid; r < 256; r += 16) {
        const float4* a = (const float4*)(src + (size_t)(p0 + r) * CC);
        *(float4*)&au[r * ES + lid * 4] = f2tf4(a[lid]);
    }
    for (int i = tid; i < 4096; i += 512) wbuf[i] = g_pkU1[t][1][i];
    __syncthreads();
    wgemm(acc, au, wbuf, mrow0, g, q, lid);

    {
        int r0 = mrow0 + g, r1 = r0 + 8;
        #pragma unroll
        for (int nt = 0; nt < 16; nt++) {
            int n = nt * 8 + q * 2;
            float b0 = ub1s[n], b1 = ub1s[n + 1];
            *(float2*)&au[r0 * ES + n] = make_float2(f2tf(fmaxf(acc[nt][0] + b0, 0.f)),
                                                     f2tf(fmaxf(acc[nt][1] + b1, 0.f)));
            *(float2*)&au[r1 * ES + n] = make_float2(f2tf(fmaxf(acc[nt][2] + b0, 0.f)),
                                                     f2tf(fmaxf(acc[nt][3] + b1, 0.f)));
        }
    }
    __syncthreads();

    for (int i = tid; i < 4096; i += 512) wbuf[i] = g_pkU2[t][i];
    __syncthreads();

    #pragma unroll
    for (int nt = 0; nt < 16; nt++)
        acc[nt][0] = acc[nt][1] = acc[nt][2] = acc[nt][3] = 0.f;
    wgemm(acc, au, wbuf, mrow0, g, q, lid);

    {
        int r0 = mrow0 + g, r1 = r0 + 8;
        const float* s0 = src + (size_t)(p0 + r0) * CC;
        const float* s1 = src + (size_t)(p0 + r1) * CC;
        float* d0 = dst + (size_t)(p0 + r0) * CC;
        float* d1 = dst + (size_t)(p0 + r1) * CC;
        float* t0 = g_featTF + (size_t)(p0 + r0) * CC;
        float* t1 = g_featTF + (size_t)(p0 + r1) * CC;
        #pragma unroll
        for (int nt = 0; nt < 16; nt++) {
            int n = nt * 8 + q * 2;
            float b0 = ub2s[n], b1 = ub2s[n + 1];
            float2 x0 = *(const float2*)&s0[n];
            float2 x1 = *(const float2*)&s1[n];
            float2 v0 = make_float2(acc[nt][0] + b0 + x0.x, acc[nt][1] + b1 + x0.y);
            float2 v1 = make_float2(acc[nt][2] + b0 + x1.x, acc[nt][3] + b1 + x1.y);
            *(float2*)&d0[n] = v0;
            *(float2*)&d1[n] = v1;
            *(float2*)&t0[n] = make_float2(f2tf(v0.x), f2tf(v0.y));
            *(float2*)&t1[n] = make_float2(f2tf(v1.x), f2tf(v1.y));
        }
    }
}

// ---------------- launch ----------------
extern "C" void kernel_launch(void* const* d_in, const int* in_sizes, int n_in,
                              void* d_out, int out_size) {
    const float* xyz      = (const float*)d_in[0];
    const float* features = (const float*)d_in[1];
    const int*   knn      = (const int*)  d_in[2];
    const float* off_W1   = (const float*)d_in[3];
    const float* off_b1   = (const float*)d_in[4];
    const float* off_W2   = (const float*)d_in[5];
    const float* off_b2   = (const float*)d_in[6];
    const float* edge_W1  = (const float*)d_in[7];
    const float* edge_b1  = (const float*)d_in[8];
    const float* edge_W2  = (const float*)d_in[9];
    const float* edge_b2  = (const float*)d_in[10];
    const float* upd_W1   = (const float*)d_in[11];
    const float* upd_b1   = (const float*)d_in[12];
    const float* upd_W2   = (const float*)d_in[13];
    const float* upd_b2   = (const float*)d_in[14];
    float* out = (float*)d_out;

    float *featA, *featB;
    cudaGetSymbolAddress((void**)&featA, g_featA);
    cudaGetSymbolAddress((void**)&featB, g_featB);

    cudaFuncSetAttribute(offset_kernel, cudaFuncAttributeMaxDynamicSharedMemorySize, O_SMEM);
    cudaFuncSetAttribute(edge_kernel,   cudaFuncAttributeMaxDynamicSharedMemorySize, E_SMEM);
    cudaFuncSetAttribute(upd_kernel,    cudaFuncAttributeMaxDynamicSharedMemorySize, U_SMEM);
    int nsm = 148;
    cudaDeviceGetAttribute(&nsm, cudaDevAttrMultiProcessorCount, 0);

    prep_kernel<<<256, 256>>>(features, off_W1, off_W2, edge_W1, edge_b1, edge_W2,
                              upd_W1, upd_W2);

    const float* src = features;
    for (int t = 0; t < TT; t++) {
        float* dst = (t == TT-1) ? out : ((t == 0) ? featA : featB);
        offset_kernel<<<BN_/256, 512, O_SMEM>>>(src, xyz, off_b1, off_b2);
        edge_kernel<<<nsm, 512, E_SMEM>>>(xyz, knn, edge_b2, t);
        upd_kernel<<<BN_/256, 512, U_SMEM>>>(src, dst, upd_b1, upd_b2, t);
        src = dst;
    }
}

// round 12
// speedup vs baseline: 1.0042x; 1.0042x over previous
#include <cuda_runtime.h>
#include <cuda_bf16.h>
#include <cstdint>

#define BB 4
#define NN 8192
#define KK 16
#define CC 128
#define TT 3
#define BN_ (BB*NN)          // 32768 points
#define CE 131               // 3 + C
#define NTILES (BN_/8)       // 4096 edge tiles (8 points x 16 nbrs = 128 rows)
#define ES 132               // padded A row stride (floats) -> conflict-free frags

// ---------------- device scratch ----------------
__device__ __align__(16) float g_featA[BN_*CC];
__device__ __align__(16) float g_featB[BN_*CC];
__device__ __align__(16) float g_featTF[BN_*CC];  // tf32-rounded mirror of current features
__device__ __align__(16) float g_agg[BN_*CC];
__device__ float  g_center[BN_*3];
__device__ float4 g_posw[TT*CC];        // {w0,w1,w2,b1} per edge output n
// packed tf32 weight fragments: idx y in [0,4096): lid=y&31, nt=(y>>5)&15, p2=y>>9
// float4 = {W[n][16p2+q], W[n][16p2+q+4], W[n][16p2+q+8], W[n][16p2+q+12]}, n=nt*8+(lid>>2), q=lid&3
__device__ float4 g_pkE1[TT][4096];
__device__ float4 g_pkE2[TT][4096];
__device__ float4 g_pkU1[TT][2][4096];
__device__ float4 g_pkU2[TT][4096];
__device__ float4 g_pkO1[4096];
__device__ float4 g_pkO2[256];          // n8 fragment (rows 3..7 zero)

// ---------------- helpers ----------------
__device__ __forceinline__ float f2tf(float x) {
    uint32_t u; asm("cvt.rna.tf32.f32 %0, %1;" : "=r"(u) : "f"(x));
    return __uint_as_float(u);
}
__device__ __forceinline__ float4 f2tf4(float4 v) {
    v.x = f2tf(v.x); v.y = f2tf(v.y); v.z = f2tf(v.z); v.w = f2tf(v.w);
    return v;
}
__device__ __forceinline__ void mma8(float* c, uint32_t a0, uint32_t a1,
                                     uint32_t a2, uint32_t a3,
                                     uint32_t b0, uint32_t b1) {
    asm volatile(
        "mma.sync.aligned.m16n8k8.row.col.f32.tf32.tf32.f32 "
        "{%0,%1,%2,%3}, {%4,%5,%6,%7}, {%8,%9}, {%0,%1,%2,%3};"
        : "+f"(c[0]), "+f"(c[1]), "+f"(c[2]), "+f"(c[3])
        : "r"(a0), "r"(a1), "r"(a2), "r"(a3), "r"(b0), "r"(b1));
}
__device__ __forceinline__ uint32_t ldu(const float* p) { return __float_as_uint(*p); }

// full warp GEMM: 16 rows x 128 N over K=128 (offset/upd).
__device__ __forceinline__ void wgemm(float acc[16][4], const float* __restrict__ abase,
                                      const float4* __restrict__ pb,
                                      int mrow0, int g, int q, int lid) {
    const float* ar0 = abase + (mrow0 + g) * ES + q;
    const float* ar1 = ar0 + 8 * ES;
    #pragma unroll
    for (int p2 = 0; p2 < 8; p2++) {
        int k0 = p2 * 16;
        uint32_t aE0 = ldu(ar0 + k0),      aE2 = ldu(ar0 + k0 + 4);
        uint32_t aE1 = ldu(ar1 + k0),      aE3 = ldu(ar1 + k0 + 4);
        uint32_t aO0 = ldu(ar0 + k0 + 8),  aO2 = ldu(ar0 + k0 + 12);
        uint32_t aO1 = ldu(ar1 + k0 + 8),  aO3 = ldu(ar1 + k0 + 12);
        const float4* pbl = pb + p2 * 512 + lid;
        #pragma unroll
        for (int nt = 0; nt < 16; nt++) {
            float4 w = pbl[nt * 32];
            mma8(acc[nt], aE0, aE1, aE2, aE3, __float_as_uint(w.x), __float_as_uint(w.y));
            mma8(acc[nt], aO0, aO1, aO2, aO3, __float_as_uint(w.z), __float_as_uint(w.w));
        }
    }
}

// edge warp GEMM: 32 rows (2x16 groups at row0) x 32 N (quarter nq) over K=128.
__device__ __forceinline__ void wgemm32(float acc[2][4][4], const float* __restrict__ abase,
                                        const float4* __restrict__ pb,
                                        int row0, int g, int q, int lid, int nq) {
    const float* a0 = abase + (row0 + g) * ES + q;
    #pragma unroll
    for (int p2 = 0; p2 < 8; p2++) {
        int k0 = p2 * 16;
        uint32_t E0[2], E1[2], E2[2], E3[2], O0[2], O1[2], O2[2], O3[2];
        #pragma unroll
        for (int mg = 0; mg < 2; mg++) {
            const float* r0p = a0 + mg * 16 * ES + k0;
            const float* r1p = r0p + 8 * ES;
            E0[mg] = ldu(r0p);      E2[mg] = ldu(r0p + 4);
            E1[mg] = ldu(r1p);      E3[mg] = ldu(r1p + 4);
            O0[mg] = ldu(r0p + 8);  O2[mg] = ldu(r0p + 12);
            O1[mg] = ldu(r1p + 8);  O3[mg] = ldu(r1p + 12);
        }
        const float4* pbl = pb + p2 * 512 + nq * 128 + lid;
        #pragma unroll
        for (int ntl = 0; ntl < 4; ntl++) {
            float4 w = pbl[ntl * 32];
            uint32_t b0 = __float_as_uint(w.x), b1 = __float_as_uint(w.y);
            uint32_t b2 = __float_as_uint(w.z), b3 = __float_as_uint(w.w);
            #pragma unroll
            for (int mg = 0; mg < 2; mg++) {
                mma8(acc[mg][ntl], E0[mg], E1[mg], E2[mg], E3[mg], b0, b1);
                mma8(acc[mg][ntl], O0[mg], O1[mg], O2[mg], O3[mg], b2, b3);
            }
        }
    }
}

// ---------------- prep ----------------
__global__ void prep_kernel(const float* __restrict__ features,
                            const float* __restrict__ off_W1, const float* __restrict__ off_W2,
                            const float* __restrict__ edge_W1, const float* __restrict__ edge_b1,
                            const float* __restrict__ edge_W2,
                            const float* __restrict__ upd_W1, const float* __restrict__ upd_W2) {
    int i0 = blockIdx.x * blockDim.x + threadIdx.x, st = gridDim.x * blockDim.x;
    for (int x = i0; x < BN_ * CC; x += st) g_featTF[x] = f2tf(features[x]);
    for (int x = i0; x < TT * 4096; x += st) {
        int t = x >> 12, y = x & 4095;
        int lid = y & 31, nt = (y >> 5) & 15, p2 = y >> 9;
        int n = nt * 8 + (lid >> 2), q = lid & 3, k = p2 * 16 + q;
        const float* s1 = edge_W1 + ((size_t)t * CC + n) * CE + 3;
        g_pkE1[t][y] = make_float4(f2tf(s1[k]), f2tf(s1[k+4]), f2tf(s1[k+8]), f2tf(s1[k+12]));
        const float* s2 = edge_W2 + ((size_t)t * CC + n) * CC;
        g_pkE2[t][y] = make_float4(f2tf(s2[k]), f2tf(s2[k+4]), f2tf(s2[k+8]), f2tf(s2[k+12]));
        const float* u1 = upd_W1 + ((size_t)t * CC + n) * 2 * CC;
        g_pkU1[t][0][y] = make_float4(f2tf(u1[k]), f2tf(u1[k+4]), f2tf(u1[k+8]), f2tf(u1[k+12]));
        const float* u1b = u1 + CC;
        g_pkU1[t][1][y] = make_float4(f2tf(u1b[k]), f2tf(u1b[k+4]), f2tf(u1b[k+8]), f2tf(u1b[k+12]));
        const float* u2 = upd_W2 + ((size_t)t * CC + n) * CC;
        g_pkU2[t][y] = make_float4(f2tf(u2[k]), f2tf(u2[k+4]), f2tf(u2[k+8]), f2tf(u2[k+12]));
    }
    for (int x = i0; x < 4096; x += st) {
        int lid = x & 31, nt = (x >> 5) & 15, p2 = x >> 9;
        int n = nt * 8 + (lid >> 2), q = lid & 3, k = p2 * 16 + q;
        const float* s = off_W1 + (size_t)n * CC;
        g_pkO1[x] = make_float4(f2tf(s[k]), f2tf(s[k+4]), f2tf(s[k+8]), f2tf(s[k+12]));
    }
    for (int x = i0; x < 256; x += st) {
        int lid = x & 31, p2 = x >> 5;
        int n = lid >> 2, q = lid & 3, k = p2 * 16 + q;
        if (n < 3) {
            const float* s = off_W2 + (size_t)n * CC;
            g_pkO2[x] = make_float4(f2tf(s[k]), f2tf(s[k+4]), f2tf(s[k+8]), f2tf(s[k+12]));
        } else {
            g_pkO2[x] = make_float4(0.f, 0.f, 0.f, 0.f);
        }
    }
    for (int x = i0; x < TT * CC; x += st) {
        int t = x >> 7, n = x & 127;
        const float* w = edge_W1 + ((size_t)t * CC + n) * CE;
        g_posw[x] = make_float4(w[0], w[1], w[2], edge_b1[t * CC + n]);
    }
}

// ---------------- offset kernel: tensor-core, 256 points/CTA ----------------
#define OO_F    0
#define OO_W1   33792
#define OO_W2   50176
#define OO_B1   51200
#define OO_B2   51328
#define O_SMEMF 51336
#define O_SMEM  (O_SMEMF*4)

__global__ void __launch_bounds__(512) offset_kernel(
    const float* __restrict__ feat, const float* __restrict__ xyz,
    const float* __restrict__ b1, const float* __restrict__ b2) {
    extern __shared__ __align__(16) float sm[];
    float*  fs  = sm + OO_F;
    float4* w1s = (float4*)(sm + OO_W1);
    float4* w2s = (float4*)(sm + OO_W2);
    float*  b1s = sm + OO_B1;
    float*  b2s = sm + OO_B2;

    const int tid = threadIdx.x, wid = tid >> 5, lid = tid & 31;
    const int g = lid >> 2, q = lid & 3;
    const int mrow0 = wid * 16;
    int p0 = blockIdx.x * 256;

    for (int i = tid; i < 4096; i += 512) w1s[i] = g_pkO1[i];
    if (tid < 256) w2s[tid] = g_pkO2[tid];
    if (tid < CC) b1s[tid] = b1[tid];
    if (tid < 3) b2s[tid] = b2[tid];
    for (int r = wid; r < 256; r += 16) {
        const float4* src = (const float4*)(feat + (size_t)(p0 + r) * CC);
        *(float4*)&fs[r * ES + lid * 4] = f2tf4(src[lid]);
    }
    __syncthreads();

    float acc[16][4];
    #pragma unroll
    for (int nt = 0; nt < 16; nt++)
        acc[nt][0] = acc[nt][1] = acc[nt][2] = acc[nt][3] = 0.f;
    wgemm(acc, fs, w1s, mrow0, g, q, lid);

    {
        int r0 = mrow0 + g, r1 = r0 + 8;
        #pragma unroll
        for (int nt = 0; nt < 16; nt++) {
            int n = nt * 8 + q * 2;
            float c0 = b1s[n], c1 = b1s[n + 1];
            *(float2*)&fs[r0 * ES + n] = make_float2(f2tf(fmaxf(acc[nt][0] + c0, 0.f)),
                                                     f2tf(fmaxf(acc[nt][1] + c1, 0.f)));
            *(float2*)&fs[r1 * ES + n] = make_float2(f2tf(fmaxf(acc[nt][2] + c0, 0.f)),
                                                     f2tf(fmaxf(acc[nt][3] + c1, 0.f)));
        }
    }

    float a2[4] = {0.f, 0.f, 0.f, 0.f};
    {
        const float* ar0 = fs + (mrow0 + g) * ES + q;
        const float* ar1 = ar0 + 8 * ES;
        #pragma unroll
        for (int p2 = 0; p2 < 8; p2++) {
            int k0 = p2 * 16;
            uint32_t aE0 = ldu(ar0 + k0),     aE2 = ldu(ar0 + k0 + 4);
            uint32_t aE1 = ldu(ar1 + k0),     aE3 = ldu(ar1 + k0 + 4);
            uint32_t aO0 = ldu(ar0 + k0 + 8), aO2 = ldu(ar0 + k0 + 12);
            uint32_t aO1 = ldu(ar1 + k0 + 8), aO3 = ldu(ar1 + k0 + 12);
            float4 w = w2s[p2 * 32 + lid];
            mma8(a2, aE0, aE1, aE2, aE3, __float_as_uint(w.x), __float_as_uint(w.y));
            mma8(a2, aO0, aO1, aO2, aO3, __float_as_uint(w.z), __float_as_uint(w.w));
        }
    }
    {
        int r0 = p0 + mrow0 + g, r1 = r0 + 8;
        if (q == 0) {
            g_center[r0*3 + 0] = xyz[r0*3 + 0] + a2[0] + b2s[0];
            g_center[r0*3 + 1] = xyz[r0*3 + 1] + a2[1] + b2s[1];
            g_center[r1*3 + 0] = xyz[r1*3 + 0] + a2[2] + b2s[0];
            g_center[r1*3 + 1] = xyz[r1*3 + 1] + a2[3] + b2s[1];
        } else if (q == 1) {
            g_center[r0*3 + 2] = xyz[r0*3 + 2] + a2[0] + b2s[2];
            g_center[r1*3 + 2] = xyz[r1*3 + 2] + a2[2] + b2s[2];
        }
    }
}

// ---------------- edge kernel: persistent, 512 threads, 32x32 warp tiles,
//                  register-prefetch pipelined gather ----------------
// smem floats: es[128*ES]=16896, w1 16384, w2 16384, relpos f4[128]=512, posw 512, eb2 128
#define EO_ES   0
#define EO_W1   16896
#define EO_W2   33280
#define EO_RP   49664
#define EO_PW   50176
#define EO_EB2  50688
#define E_SMEMF 50816
#define E_SMEM  (E_SMEMF*4)

__global__ void __launch_bounds__(512, 1) edge_kernel(
    const float* __restrict__ xyz, const int* __restrict__ knn,
    const float* __restrict__ eb2, int t) {
    extern __shared__ __align__(16) float sm[];
    float*  es   = sm + EO_ES;
    float4* w1s  = (float4*)(sm + EO_W1);
    float4* w2s  = (float4*)(sm + EO_W2);
    float4* relpos = (float4*)(sm + EO_RP);
    float4* posw   = (float4*)(sm + EO_PW);
    float*  eb2s   = sm + EO_EB2;

    const int tid = threadIdx.x, wid = tid >> 5, lid = tid & 31;
    const int g = lid >> 2, q = lid & 3;
    const int rw2 = wid & 3;         // row group of 32 (= 2 points)
    const int nq  = wid >> 2;        // N quarter
    const int row0 = rw2 * 32;
    const int grow = tid >> 2;       // gather row (0..127)
    const int seg  = tid & 3;        // 128B segment within row (seg*8 float4s)

    for (int i = tid; i < 4096; i += 512) { w1s[i] = g_pkE1[t][i]; w2s[i] = g_pkE2[t][i]; }
    if (tid < CC) { posw[tid] = g_posw[t * CC + tid]; eb2s[tid] = eb2[t * CC + tid]; }

    // prefetch state for the tile about to be processed
    float4 pf[8];                    // feature segment (128B)
    float  pxyz[3], pctr[3];         // relpos inputs (tid<128 only meaningful)

    // prologue: prefetch first tile
    int tt = blockIdx.x;
    if (tt < NTILES) {
        int p0 = tt * 8, base = p0 & ~(NN - 1);
        int idx = __ldg(&knn[(size_t)p0 * KK + grow]);
        const float4* src = (const float4*)(g_featTF + (size_t)(base + idx) * CC) + seg * 8;
        #pragma unroll
        for (int j = 0; j < 8; j++) pf[j] = __ldg(&src[j]);
        if (tid < 128) {
            int p = p0 + (tid >> 4);
            int nb = base + __ldg(&knn[(size_t)p0 * KK + tid]);
            pxyz[0] = __ldg(&xyz[nb*3+0]); pxyz[1] = __ldg(&xyz[nb*3+1]); pxyz[2] = __ldg(&xyz[nb*3+2]);
            pctr[0] = __ldg(&g_center[p*3+0]); pctr[1] = __ldg(&g_center[p*3+1]); pctr[2] = __ldg(&g_center[p*3+2]);
        }
    }

    for (; tt < NTILES; tt += gridDim.x) {
        int p0 = tt * 8;
        __syncthreads();   // previous tile's compute (and first-tile weight fill) complete

        // store prefetched data for THIS tile
        {
            float4* dst = (float4*)&es[grow * ES + seg * 32];
            #pragma unroll
            for (int j = 0; j < 8; j++) dst[j] = pf[j];
        }
        if (tid < 128)
            relpos[tid] = make_float4(pxyz[0] - pctr[0], pxyz[1] - pctr[1],
                                      pxyz[2] - pctr[2], 0.f);
        __syncthreads();

        // layer 1 (feat part)
        float acc[2][4][4];
        #pragma unroll
        for (int mg = 0; mg < 2; mg++)
            #pragma unroll
            for (int ntl = 0; ntl < 4; ntl++)
                acc[mg][ntl][0] = acc[mg][ntl][1] = acc[mg][ntl][2] = acc[mg][ntl][3] = 0.f;
        wgemm32(acc, es, w1s, row0, g, q, lid, nq);

        // epilogue1: + rel_pos·W + b1 (exact fp32), ReLU, tf32 -> own rows/cols
        #pragma unroll
        for (int mg = 0; mg < 2; mg++) {
            int r0 = row0 + mg * 16 + g, r1 = r0 + 8;
            float4 rp0 = relpos[r0], rp1 = relpos[r1];
            #pragma unroll
            for (int ntl = 0; ntl < 4; ntl++) {
                int n = nq * 32 + ntl * 8 + q * 2;
                float4 pwa = posw[n], pwb = posw[n + 1];
                float pa0 = rp0.x*pwa.x + rp0.y*pwa.y + rp0.z*pwa.z + pwa.w;
                float pb0 = rp0.x*pwb.x + rp0.y*pwb.y + rp0.z*pwb.z + pwb.w;
                float pa1 = rp1.x*pwa.x + rp1.y*pwa.y + rp1.z*pwa.z + pwa.w;
                float pb1 = rp1.x*pwb.x + rp1.y*pwb.y + rp1.z*pwb.z + pwb.w;
                *(float2*)&es[r0 * ES + n] = make_float2(f2tf(fmaxf(acc[mg][ntl][0] + pa0, 0.f)),
                                                         f2tf(fmaxf(acc[mg][ntl][1] + pb0, 0.f)));
                *(float2*)&es[r1 * ES + n] = make_float2(f2tf(fmaxf(acc[mg][ntl][2] + pa1, 0.f)),
                                                         f2tf(fmaxf(acc[mg][ntl][3] + pb1, 0.f)));
            }
        }
        __syncthreads();

        // prefetch NEXT tile (latency hidden behind layer 2)
        int nxt = tt + (int)gridDim.x;
        if (nxt < NTILES) {
            int np0 = nxt * 8, nbase = np0 & ~(NN - 1);
            int idx = __ldg(&knn[(size_t)np0 * KK + grow]);
            const float4* src = (const float4*)(g_featTF + (size_t)(nbase + idx) * CC) + seg * 8;
            #pragma unroll
            for (int j = 0; j < 8; j++) pf[j] = __ldg(&src[j]);
            if (tid < 128) {
                int p = np0 + (tid >> 4);
                int nb = nbase + __ldg(&knn[(size_t)np0 * KK + tid]);
                pxyz[0] = __ldg(&xyz[nb*3+0]); pxyz[1] = __ldg(&xyz[nb*3+1]); pxyz[2] = __ldg(&xyz[nb*3+2]);
                pctr[0] = __ldg(&g_center[p*3+0]); pctr[1] = __ldg(&g_center[p*3+1]); pctr[2] = __ldg(&g_center[p*3+2]);
            }
        }

        // layer 2
        #pragma unroll
        for (int mg = 0; mg < 2; mg++)
            #pragma unroll
            for (int ntl = 0; ntl < 4; ntl++)
                acc[mg][ntl][0] = acc[mg][ntl][1] = acc[mg][ntl][2] = acc[mg][ntl][3] = 0.f;
        wgemm32(acc, es, w2s, row0, g, q, lid, nq);

        // epilogue2: per mg-group = one point's 16 neighbor rows -> max, +b2
        #pragma unroll
        for (int mg = 0; mg < 2; mg++) {
            int p = p0 + rw2 * 2 + mg;
            float* outp = g_agg + (size_t)p * CC;
            #pragma unroll
            for (int ntl = 0; ntl < 4; ntl++) {
                float m0 = fmaxf(acc[mg][ntl][0], acc[mg][ntl][2]);
                float m1 = fmaxf(acc[mg][ntl][1], acc[mg][ntl][3]);
                #pragma unroll
                for (int s = 4; s <= 16; s <<= 1) {
                    m0 = fmaxf(m0, __shfl_xor_sync(0xffffffffu, m0, s));
                    m1 = fmaxf(m1, __shfl_xor_sync(0xffffffffu, m1, s));
                }
                if (g == 0) {
                    int n = nq * 32 + ntl * 8 + q * 2;
                    *(float2*)&outp[n] = make_float2(m0 + eb2s[n], m1 + eb2s[n + 1]);
                }
            }
        }
    }
}

// ---------------- upd kernel: 512 threads, 256 points/CTA ----------------
#define UO_A    0
#define UO_W    33792
#define UO_B1   50176
#define UO_B2   50304
#define U_SMEMF 50432
#define U_SMEM  (U_SMEMF*4)

__global__ void __launch_bounds__(512) upd_kernel(
    const float* __restrict__ src, float* __restrict__ dst,
    const float* __restrict__ ub1, const float* __restrict__ ub2, int t) {
    extern __shared__ __align__(16) float sm[];
    float*  au   = sm + UO_A;
    float4* wbuf = (float4*)(sm + UO_W);
    float*  ub1s = sm + UO_B1;
    float*  ub2s = sm + UO_B2;

    const int tid = threadIdx.x, wid = tid >> 5, lid = tid & 31;
    const int g = lid >> 2, q = lid & 3;
    const int mrow0 = wid * 16;
    int p0 = blockIdx.x * 256;

    for (int r = wid; r < 256; r += 16) {
        const float4* a = (const float4*)(g_agg + (size_t)(p0 + r) * CC);
        *(float4*)&au[r * ES + lid * 4] = f2tf4(a[lid]);
    }
    for (int i = tid; i < 4096; i += 512) wbuf[i] = g_pkU1[t][0][i];
    if (tid < CC) { ub1s[tid] = ub1[t*CC + tid]; ub2s[tid] = ub2[t*CC + tid]; }
    __syncthreads();

    float acc[16][4];
    #pragma unroll
    for (int nt = 0; nt < 16; nt++)
        acc[nt][0] = acc[nt][1] = acc[nt][2] = acc[nt][3] = 0.f;
    wgemm(acc, au, wbuf, mrow0, g, q, lid);
    __syncthreads();

    for (int r = wid; r < 256; r += 16) {
        const float4* a = (const float4*)(src + (size_t)(p0 + r) * CC);
        *(float4*)&au[r * ES + lid * 4] = f2tf4(a[lid]);
    }
    for (int i = tid; i < 4096; i += 512) wbuf[i] = g_pkU1[t][1][i];
    __syncthreads();
    wgemm(acc, au, wbuf, mrow0, g, q, lid);

    {
        int r0 = mrow0 + g, r1 = r0 + 8;
        #pragma unroll
        for (int nt = 0; nt < 16; nt++) {
            int n = nt * 8 + q * 2;
            float b0 = ub1s[n], b1 = ub1s[n + 1];
            *(float2*)&au[r0 * ES + n] = make_float2(f2tf(fmaxf(acc[nt][0] + b0, 0.f)),
                                                     f2tf(fmaxf(acc[nt][1] + b1, 0.f)));
            *(float2*)&au[r1 * ES + n] = make_float2(f2tf(fmaxf(acc[nt][2] + b0, 0.f)),
                                                     f2tf(fmaxf(acc[nt][3] + b1, 0.f)));
        }
    }
    __syncthreads();

    for (int i = tid; i < 4096; i += 512) wbuf[i] = g_pkU2[t][i];
    __syncthreads();

    #pragma unroll
    for (int nt = 0; nt < 16; nt++)
        acc[nt][0] = acc[nt][1] = acc[nt][2] = acc[nt][3] = 0.f;
    wgemm(acc, au, wbuf, mrow0, g, q, lid);

    {
        int r0 = mrow0 + g, r1 = r0 + 8;
        const float* s0 = src + (size_t)(p0 + r0) * CC;
        const float* s1 = src + (size_t)(p0 + r1) * CC;
        float* d0 = dst + (size_t)(p0 + r0) * CC;
        float* d1 = dst + (size_t)(p0 + r1) * CC;
        float* t0 = g_featTF + (size_t)(p0 + r0) * CC;
        float* t1 = g_featTF + (size_t)(p0 + r1) * CC;
        #pragma unroll
        for (int nt = 0; nt < 16; nt++) {
            int n = nt * 8 + q * 2;
            float b0 = ub2s[n], b1 = ub2s[n + 1];
            float2 x0 = *(const float2*)&s0[n];
            float2 x1 = *(const float2*)&s1[n];
            float2 v0 = make_float2(acc[nt][0] + b0 + x0.x, acc[nt][1] + b1 + x0.y);
            float2 v1 = make_float2(acc[nt][2] + b0 + x1.x, acc[nt][3] + b1 + x1.y);
            *(float2*)&d0[n] = v0;
            *(float2*)&d1[n] = v1;
            *(float2*)&t0[n] = make_float2(f2tf(v0.x), f2tf(v0.y));
            *(float2*)&t1[n] = make_float2(f2tf(v1.x), f2tf(v1.y));
        }
    }
}

// ---------------- launch ----------------
extern "C" void kernel_launch(void* const* d_in, const int* in_sizes, int n_in,
                              void* d_out, int out_size) {
    const float* xyz      = (const float*)d_in[0];
    const float* features = (const float*)d_in[1];
    const int*   knn      = (const int*)  d_in[2];
    const float* off_W1   = (const float*)d_in[3];
    const float* off_b1   = (const float*)d_in[4];
    const float* off_W2   = (const float*)d_in[5];
    const float* off_b2   = (const float*)d_in[6];
    const float* edge_W1  = (const float*)d_in[7];
    const float* edge_b1  = (const float*)d_in[8];
    const float* edge_W2  = (const float*)d_in[9];
    const float* edge_b2  = (const float*)d_in[10];
    const float* upd_W1   = (const float*)d_in[11];
    const float* upd_b1   = (const float*)d_in[12];
    const float* upd_W2   = (const float*)d_in[13];
    const float* upd_b2   = (const float*)d_in[14];
    float* out = (float*)d_out;

    float *featA, *featB;
    cudaGetSymbolAddress((void**)&featA, g_featA);
    cudaGetSymbolAddress((void**)&featB, g_featB);

    cudaFuncSetAttribute(offset_kernel, cudaFuncAttributeMaxDynamicSharedMemorySize, O_SMEM);
    cudaFuncSetAttribute(edge_kernel,   cudaFuncAttributeMaxDynamicSharedMemorySize, E_SMEM);
    cudaFuncSetAttribute(upd_kernel,    cudaFuncAttributeMaxDynamicSharedMemorySize, U_SMEM);
    int nsm = 148;
    cudaDeviceGetAttribute(&nsm, cudaDevAttrMultiProcessorCount, 0);

    prep_kernel<<<256, 256>>>(features, off_W1, off_W2, edge_W1, edge_b1, edge_W2,
                              upd_W1, upd_W2);

    const float* src = features;
    for (int t = 0; t < TT; t++) {
        float* dst = (t == TT-1) ? out : ((t == 0) ? featA : featB);
        offset_kernel<<<BN_/256, 512, O_SMEM>>>(src, xyz, off_b1, off_b2);
        edge_kernel<<<nsm, 512, E_SMEM>>>(xyz, knn, edge_b2, t);
        upd_kernel<<<BN_/256, 512, U_SMEM>>>(src, dst, upd_b1, upd_b2, t);
        src = dst;
    }
}

// round 14
// speedup vs baseline: 1.1242x; 1.1195x over previous
#include <cuda_runtime.h>
#include <cuda_bf16.h>
#include <cstdint>

#define BB 4
#define NN 8192
#define KK 16
#define CC 128
#define TT 3
#define BN_ (BB*NN)          // 32768 points
#define CE 131               // 3 + C
#define NTILES (BN_/8)       // 4096 edge tiles (8 points x 16 nbrs = 128 rows)
#define ES 132               // padded A row stride (floats) -> conflict-free frags

// ---------------- device scratch ----------------
__device__ __align__(16) float g_featA[BN_*CC];
__device__ __align__(16) float g_featB[BN_*CC];
__device__ __align__(16) float g_featTF[BN_*CC];  // tf32-rounded mirror of current features
__device__ __align__(16) float g_agg[BN_*CC];
__device__ float  g_center[BN_*3];
__device__ float4 g_posw[TT*CC];        // {w0,w1,w2,b1} per edge output n
// packed tf32 weight fragments: idx y in [0,4096): lid=y&31, nt=(y>>5)&15, p2=y>>9
// float4 = {W[n][16p2+q], W[n][16p2+q+4], W[n][16p2+q+8], W[n][16p2+q+12]}, n=nt*8+(lid>>2), q=lid&3
__device__ float4 g_pkE1[TT][4096];
__device__ float4 g_pkE2[TT][4096];
__device__ float4 g_pkU1[TT][2][4096];
__device__ float4 g_pkU2[TT][4096];
__device__ float4 g_pkO1[4096];
__device__ float4 g_pkO2[256];          // n8 fragment (rows 3..7 zero)

// ---------------- helpers ----------------
__device__ __forceinline__ float f2tf(float x) {
    uint32_t u; asm("cvt.rna.tf32.f32 %0, %1;" : "=r"(u) : "f"(x));
    return __uint_as_float(u);
}
__device__ __forceinline__ float4 f2tf4(float4 v) {
    v.x = f2tf(v.x); v.y = f2tf(v.y); v.z = f2tf(v.z); v.w = f2tf(v.w);
    return v;
}
__device__ __forceinline__ uint32_t s2u(const void* p) {
    uint32_t a;
    asm("{ .reg .u64 t; cvta.to.shared.u64 t, %1; cvt.u32.u64 %0, t; }" : "=r"(a) : "l"(p));
    return a;
}
__device__ __forceinline__ void cpasync16(uint32_t dst, const void* src) {
    asm volatile("cp.async.cg.shared.global [%0], [%1], 16;" :: "r"(dst), "l"(src));
}
#define CP_COMMIT() asm volatile("cp.async.commit_group;" ::: "memory")
#define CP_WAIT0()  asm volatile("cp.async.wait_group 0;" ::: "memory")

__device__ __forceinline__ void mma8(float* c, uint32_t a0, uint32_t a1,
                                     uint32_t a2, uint32_t a3,
                                     uint32_t b0, uint32_t b1) {
    asm volatile(
        "mma.sync.aligned.m16n8k8.row.col.f32.tf32.tf32.f32 "
        "{%0,%1,%2,%3}, {%4,%5,%6,%7}, {%8,%9}, {%0,%1,%2,%3};"
        : "+f"(c[0]), "+f"(c[1]), "+f"(c[2]), "+f"(c[3])
        : "r"(a0), "r"(a1), "r"(a2), "r"(a3), "r"(b0), "r"(b1));
}
__device__ __forceinline__ uint32_t ldu(const float* p) { return __float_as_uint(*p); }

// full warp GEMM: 16 rows x 128 N over K=128, B fragments in smem (offset/upd).
__device__ __forceinline__ void wgemm(float acc[16][4], const float* __restrict__ abase,
                                      const float4* __restrict__ pb,
                                      int mrow0, int g, int q, int lid) {
    const float* ar0 = abase + (mrow0 + g) * ES + q;
    const float* ar1 = ar0 + 8 * ES;
    #pragma unroll
    for (int p2 = 0; p2 < 8; p2++) {
        int k0 = p2 * 16;
        uint32_t aE0 = ldu(ar0 + k0),      aE2 = ldu(ar0 + k0 + 4);
        uint32_t aE1 = ldu(ar1 + k0),      aE3 = ldu(ar1 + k0 + 4);
        uint32_t aO0 = ldu(ar0 + k0 + 8),  aO2 = ldu(ar0 + k0 + 12);
        uint32_t aO1 = ldu(ar1 + k0 + 8),  aO3 = ldu(ar1 + k0 + 12);
        const float4* pbl = pb + p2 * 512 + lid;
        #pragma unroll
        for (int nt = 0; nt < 16; nt++) {
            float4 w = pbl[nt * 32];
            mma8(acc[nt], aE0, aE1, aE2, aE3, __float_as_uint(w.x), __float_as_uint(w.y));
            mma8(acc[nt], aO0, aO1, aO2, aO3, __float_as_uint(w.z), __float_as_uint(w.w));
        }
    }
}

// edge warp GEMM: 32 rows x 32 N (quarter nq) over K=128, B fragments in GLOBAL (L2-hot).
__device__ __forceinline__ void wgemm32g(float acc[2][4][4], const float* __restrict__ abase,
                                         const float4* __restrict__ pb,
                                         int row0, int g, int q, int lid, int nq) {
    const float* a0 = abase + (row0 + g) * ES + q;
    #pragma unroll
    for (int p2 = 0; p2 < 8; p2++) {
        int k0 = p2 * 16;
        uint32_t E0[2], E1[2], E2[2], E3[2], O0[2], O1[2], O2[2], O3[2];
        #pragma unroll
        for (int mg = 0; mg < 2; mg++) {
            const float* r0p = a0 + mg * 16 * ES + k0;
            const float* r1p = r0p + 8 * ES;
            E0[mg] = ldu(r0p);      E2[mg] = ldu(r0p + 4);
            E1[mg] = ldu(r1p);      E3[mg] = ldu(r1p + 4);
            O0[mg] = ldu(r0p + 8);  O2[mg] = ldu(r0p + 12);
            O1[mg] = ldu(r1p + 8);  O3[mg] = ldu(r1p + 12);
        }
        const float4* pbl = pb + p2 * 512 + nq * 128 + lid;
        #pragma unroll
        for (int ntl = 0; ntl < 4; ntl++) {
            float4 w = __ldg(&pbl[ntl * 32]);
            uint32_t b0 = __float_as_uint(w.x), b1 = __float_as_uint(w.y);
            uint32_t b2 = __float_as_uint(w.z), b3 = __float_as_uint(w.w);
            #pragma unroll
            for (int mg = 0; mg < 2; mg++) {
                mma8(acc[mg][ntl], E0[mg], E1[mg], E2[mg], E3[mg], b0, b1);
                mma8(acc[mg][ntl], O0[mg], O1[mg], O2[mg], O3[mg], b2, b3);
            }
        }
    }
}

// ---------------- prep ----------------
__global__ void prep_kernel(const float* __restrict__ features,
                            const float* __restrict__ off_W1, const float* __restrict__ off_W2,
                            const float* __restrict__ edge_W1, const float* __restrict__ edge_b1,
                            const float* __restrict__ edge_W2,
                            const float* __restrict__ upd_W1, const float* __restrict__ upd_W2) {
    int i0 = blockIdx.x * blockDim.x + threadIdx.x, st = gridDim.x * blockDim.x;
    for (int x = i0; x < BN_ * CC; x += st) g_featTF[x] = f2tf(features[x]);
    for (int x = i0; x < TT * 4096; x += st) {
        int t = x >> 12, y = x & 4095;
        int lid = y & 31, nt = (y >> 5) & 15, p2 = y >> 9;
        int n = nt * 8 + (lid >> 2), q = lid & 3, k = p2 * 16 + q;
        const float* s1 = edge_W1 + ((size_t)t * CC + n) * CE + 3;
        g_pkE1[t][y] = make_float4(f2tf(s1[k]), f2tf(s1[k+4]), f2tf(s1[k+8]), f2tf(s1[k+12]));
        const float* s2 = edge_W2 + ((size_t)t * CC + n) * CC;
        g_pkE2[t][y] = make_float4(f2tf(s2[k]), f2tf(s2[k+4]), f2tf(s2[k+8]), f2tf(s2[k+12]));
        const float* u1 = upd_W1 + ((size_t)t * CC + n) * 2 * CC;
        g_pkU1[t][0][y] = make_float4(f2tf(u1[k]), f2tf(u1[k+4]), f2tf(u1[k+8]), f2tf(u1[k+12]));
        const float* u1b = u1 + CC;
        g_pkU1[t][1][y] = make_float4(f2tf(u1b[k]), f2tf(u1b[k+4]), f2tf(u1b[k+8]), f2tf(u1b[k+12]));
        const float* u2 = upd_W2 + ((size_t)t * CC + n) * CC;
        g_pkU2[t][y] = make_float4(f2tf(u2[k]), f2tf(u2[k+4]), f2tf(u2[k+8]), f2tf(u2[k+12]));
    }
    for (int x = i0; x < 4096; x += st) {
        int lid = x & 31, nt = (x >> 5) & 15, p2 = x >> 9;
        int n = nt * 8 + (lid >> 2), q = lid & 3, k = p2 * 16 + q;
        const float* s = off_W1 + (size_t)n * CC;
        g_pkO1[x] = make_float4(f2tf(s[k]), f2tf(s[k+4]), f2tf(s[k+8]), f2tf(s[k+12]));
    }
    for (int x = i0; x < 256; x += st) {
        int lid = x & 31, p2 = x >> 5;
        int n = lid >> 2, q = lid & 3, k = p2 * 16 + q;
        if (n < 3) {
            const float* s = off_W2 + (size_t)n * CC;
            g_pkO2[x] = make_float4(f2tf(s[k]), f2tf(s[k+4]), f2tf(s[k+8]), f2tf(s[k+12]));
        } else {
            g_pkO2[x] = make_float4(0.f, 0.f, 0.f, 0.f);
        }
    }
    for (int x = i0; x < TT * CC; x += st) {
        int t = x >> 7, n = x & 127;
        const float* w = edge_W1 + ((size_t)t * CC + n) * CE;
        g_posw[x] = make_float4(w[0], w[1], w[2], edge_b1[t * CC + n]);
    }
}

// ---------------- offset kernel: tensor-core, 256 points/CTA ----------------
#define OO_F    0
#define OO_W1   33792
#define OO_W2   50176
#define OO_B1   51200
#define OO_B2   51328
#define O_SMEMF 51336
#define O_SMEM  (O_SMEMF*4)

__global__ void __launch_bounds__(512) offset_kernel(
    const float* __restrict__ feat, const float* __restrict__ xyz,
    const float* __restrict__ b1, const float* __restrict__ b2) {
    extern __shared__ __align__(16) float sm[];
    float*  fs  = sm + OO_F;
    float4* w1s = (float4*)(sm + OO_W1);
    float4* w2s = (float4*)(sm + OO_W2);
    float*  b1s = sm + OO_B1;
    float*  b2s = sm + OO_B2;

    const int tid = threadIdx.x, wid = tid >> 5, lid = tid & 31;
    const int g = lid >> 2, q = lid & 3;
    const int mrow0 = wid * 16;
    int p0 = blockIdx.x * 256;

    for (int i = tid; i < 4096; i += 512) w1s[i] = g_pkO1[i];
    if (tid < 256) w2s[tid] = g_pkO2[tid];
    if (tid < CC) b1s[tid] = b1[tid];
    if (tid < 3) b2s[tid] = b2[tid];
    for (int r = wid; r < 256; r += 16) {
        const float4* src = (const float4*)(feat + (size_t)(p0 + r) * CC);
        *(float4*)&fs[r * ES + lid * 4] = f2tf4(src[lid]);
    }
    __syncthreads();

    float acc[16][4];
    #pragma unroll
    for (int nt = 0; nt < 16; nt++)
        acc[nt][0] = acc[nt][1] = acc[nt][2] = acc[nt][3] = 0.f;
    wgemm(acc, fs, w1s, mrow0, g, q, lid);

    {
        int r0 = mrow0 + g, r1 = r0 + 8;
        #pragma unroll
        for (int nt = 0; nt < 16; nt++) {
            int n = nt * 8 + q * 2;
            float c0 = b1s[n], c1 = b1s[n + 1];
            *(float2*)&fs[r0 * ES + n] = make_float2(f2tf(fmaxf(acc[nt][0] + c0, 0.f)),
                                                     f2tf(fmaxf(acc[nt][1] + c1, 0.f)));
            *(float2*)&fs[r1 * ES + n] = make_float2(f2tf(fmaxf(acc[nt][2] + c0, 0.f)),
                                                     f2tf(fmaxf(acc[nt][3] + c1, 0.f)));
        }
    }

    float a2[4] = {0.f, 0.f, 0.f, 0.f};
    {
        const float* ar0 = fs + (mrow0 + g) * ES + q;
        const float* ar1 = ar0 + 8 * ES;
        #pragma unroll
        for (int p2 = 0; p2 < 8; p2++) {
            int k0 = p2 * 16;
            uint32_t aE0 = ldu(ar0 + k0),     aE2 = ldu(ar0 + k0 + 4);
            uint32_t aE1 = ldu(ar1 + k0),     aE3 = ldu(ar1 + k0 + 4);
            uint32_t aO0 = ldu(ar0 + k0 + 8), aO2 = ldu(ar0 + k0 + 12);
            uint32_t aO1 = ldu(ar1 + k0 + 8), aO3 = ldu(ar1 + k0 + 12);
            float4 w = w2s[p2 * 32 + lid];
            mma8(a2, aE0, aE1, aE2, aE3, __float_as_uint(w.x), __float_as_uint(w.y));
            mma8(a2, aO0, aO1, aO2, aO3, __float_as_uint(w.z), __float_as_uint(w.w));
        }
    }
    {
        int r0 = p0 + mrow0 + g, r1 = r0 + 8;
        if (q == 0) {
            g_center[r0*3 + 0] = xyz[r0*3 + 0] + a2[0] + b2s[0];
            g_center[r0*3 + 1] = xyz[r0*3 + 1] + a2[1] + b2s[1];
            g_center[r1*3 + 0] = xyz[r1*3 + 0] + a2[2] + b2s[0];
            g_center[r1*3 + 1] = xyz[r1*3 + 1] + a2[3] + b2s[1];
        } else if (q == 1) {
            g_center[r0*3 + 2] = xyz[r0*3 + 2] + a2[0] + b2s[2];
            g_center[r1*3 + 2] = xyz[r1*3 + 2] + a2[2] + b2s[2];
        }
    }
}

// ---------------- edge kernel: persistent, double-buffered 128-row tiles,
//                  B fragments from L2, race-free epilogue ----------------
// smem floats: es[2][128*ES]=33792, relpos f4[128]=512, posw f4[128]=512, eb2[128]
#define EO_ES   0
#define EO_RP   33792
#define EO_PW   34304
#define EO_EB2  34816
#define E_SMEMF 34944
#define E_SMEM  (E_SMEMF*4)
#define EBUF    (128*ES)

__global__ void __launch_bounds__(512, 1) edge_kernel(
    const float* __restrict__ xyz, const int* __restrict__ knn,
    const float* __restrict__ eb2, int t) {
    extern __shared__ __align__(16) float sm[];
    float*  es0  = sm + EO_ES;
    float4* relpos = (float4*)(sm + EO_RP);
    float4* posw   = (float4*)(sm + EO_PW);
    float*  eb2s   = sm + EO_EB2;

    const int tid = threadIdx.x, wid = tid >> 5, lid = tid & 31;
    const int g = lid >> 2, q = lid & 3;
    const int rw2 = wid & 3;         // row group of 32 (= 2 points)
    const int nq  = wid >> 2;        // N quarter
    const int row0 = rw2 * 32;
    const int grow = tid >> 2;       // gather row (0..127)
    const int seg  = tid & 3;        // 128B segment within 512B row
    const uint32_t es_base = s2u(es0);
    const float4* gw1 = g_pkE1[t];
    const float4* gw2 = g_pkE2[t];

    if (tid < CC) { posw[tid] = g_posw[t * CC + tid]; eb2s[tid] = eb2[t * CC + tid]; }

    int tt = blockIdx.x;
    int cur = 0;
    // prologue: prefetch first tile into buf 0
    if (tt < NTILES) {
        int p0 = tt * 8, base = p0 & ~(NN - 1);
        int idx = __ldg(&knn[(size_t)p0 * KK + grow]);
        const float* src = g_featTF + (size_t)(base + idx) * CC + seg * 32;
        uint32_t dst = es_base + (uint32_t)(grow * ES + seg * 32) * 4;
        #pragma unroll
        for (int j = 0; j < 8; j++) cpasync16(dst + j * 16, src + j * 4);
    }
    CP_COMMIT();

    for (; tt < NTILES; tt += gridDim.x) {
        int p0 = tt * 8, base = p0 & ~(NN - 1);
        CP_WAIT0();          // current tile's gather landed
        __syncthreads();     // prev tile compute done; posw/eb2s visible (first iter)

        // prefetch NEXT tile into the other buffer (overlaps all of this tile's compute)
        int nxt = tt + (int)gridDim.x;
        if (nxt < NTILES) {
            int np0 = nxt * 8, nbase = np0 & ~(NN - 1);
            int idx = __ldg(&knn[(size_t)np0 * KK + grow]);
            const float* src = g_featTF + (size_t)(nbase + idx) * CC + seg * 32;
            uint32_t dst = es_base + (uint32_t)((cur ^ 1) * EBUF + grow * ES + seg * 32) * 4;
            #pragma unroll
            for (int j = 0; j < 8; j++) cpasync16(dst + j * 16, src + j * 4);
        }
        CP_COMMIT();

        float* es = es0 + cur * EBUF;

        // relpos (same arithmetic/order as round 10; visible after the next sync)
        if (tid < 128) {
            int r = tid, p = p0 + (r >> 4);
            int nb = base + __ldg(&knn[(size_t)p0 * KK + r]);
            float cx = g_center[p*3+0], cy = g_center[p*3+1], cz = g_center[p*3+2];
            relpos[r] = make_float4(xyz[nb*3+0]-cx, xyz[nb*3+1]-cy, xyz[nb*3+2]-cz, 0.f);
        }

        // layer 1 (feat part), B from L2
        float acc[2][4][4];
        #pragma unroll
        for (int mg = 0; mg < 2; mg++)
            #pragma unroll
            for (int ntl = 0; ntl < 4; ntl++)
                acc[mg][ntl][0] = acc[mg][ntl][1] = acc[mg][ntl][2] = acc[mg][ntl][3] = 0.f;
        wgemm32g(acc, es, gw1, row0, g, q, lid, nq);
        __syncthreads();   // ALL warps done reading es (fixes the row-sharing race); relpos visible

        // epilogue1: + rel_pos·W + b1 (exact fp32), ReLU, tf32 -> own rows/cols of es
        #pragma unroll
        for (int mg = 0; mg < 2; mg++) {
            int r0 = row0 + mg * 16 + g, r1 = r0 + 8;
            float4 rp0 = relpos[r0], rp1 = relpos[r1];
            #pragma unroll
            for (int ntl = 0; ntl < 4; ntl++) {
                int n = nq * 32 + ntl * 8 + q * 2;
                float4 pwa = posw[n], pwb = posw[n + 1];
                float pa0 = rp0.x*pwa.x + rp0.y*pwa.y + rp0.z*pwa.z + pwa.w;
                float pb0 = rp0.x*pwb.x + rp0.y*pwb.y + rp0.z*pwb.z + pwb.w;
                float pa1 = rp1.x*pwa.x + rp1.y*pwa.y + rp1.z*pwa.z + pwa.w;
                float pb1 = rp1.x*pwb.x + rp1.y*pwb.y + rp1.z*pwb.z + pwb.w;
                *(float2*)&es[r0 * ES + n] = make_float2(f2tf(fmaxf(acc[mg][ntl][0] + pa0, 0.f)),
                                                         f2tf(fmaxf(acc[mg][ntl][1] + pb0, 0.f)));
                *(float2*)&es[r1 * ES + n] = make_float2(f2tf(fmaxf(acc[mg][ntl][2] + pa1, 0.f)),
                                                         f2tf(fmaxf(acc[mg][ntl][3] + pb1, 0.f)));
            }
        }
        __syncthreads();   // post-ReLU tile complete

        // layer 2, B from L2
        #pragma unroll
        for (int mg = 0; mg < 2; mg++)
            #pragma unroll
            for (int ntl = 0; ntl < 4; ntl++)
                acc[mg][ntl][0] = acc[mg][ntl][1] = acc[mg][ntl][2] = acc[mg][ntl][3] = 0.f;
        wgemm32g(acc, es, gw2, row0, g, q, lid, nq);

        // epilogue2: per mg-group = one point's 16 neighbor rows -> max, +b2
        #pragma unroll
        for (int mg = 0; mg < 2; mg++) {
            int p = p0 + rw2 * 2 + mg;
            float* outp = g_agg + (size_t)p * CC;
            #pragma unroll
            for (int ntl = 0; ntl < 4; ntl++) {
                float m0 = fmaxf(acc[mg][ntl][0], acc[mg][ntl][2]);
                float m1 = fmaxf(acc[mg][ntl][1], acc[mg][ntl][3]);
                #pragma unroll
                for (int s = 4; s <= 16; s <<= 1) {
                    m0 = fmaxf(m0, __shfl_xor_sync(0xffffffffu, m0, s));
                    m1 = fmaxf(m1, __shfl_xor_sync(0xffffffffu, m1, s));
                }
                if (g == 0) {
                    int n = nq * 32 + ntl * 8 + q * 2;
                    *(float2*)&outp[n] = make_float2(m0 + eb2s[n], m1 + eb2s[n + 1]);
                }
            }
        }
        cur ^= 1;
    }
}

// ---------------- upd kernel: 512 threads, 256 points/CTA ----------------
#define UO_A    0
#define UO_W    33792
#define UO_B1   50176
#define UO_B2   50304
#define U_SMEMF 50432
#define U_SMEM  (U_SMEMF*4)

__global__ void __launch_bounds__(512) upd_kernel(
    const float* __restrict__ src, float* __restrict__ dst,
    const float* __restrict__ ub1, const float* __restrict__ ub2, int t) {
    extern __shared__ __align__(16) float sm[];
    float*  au   = sm + UO_A;
    float4* wbuf = (float4*)(sm + UO_W);
    float*  ub1s = sm + UO_B1;
    float*  ub2s = sm + UO_B2;

    const int tid = threadIdx.x, wid = tid >> 5, lid = tid & 31;
    const int g = lid >> 2, q = lid & 3;
    const int mrow0 = wid * 16;
    int p0 = blockIdx.x * 256;

    for (int r = wid; r < 256; r += 16) {
        const float4* a = (const float4*)(g_agg + (size_t)(p0 + r) * CC);
        *(float4*)&au[r * ES + lid * 4] = f2tf4(a[lid]);
    }
    for (int i = tid; i < 4096; i += 512) wbuf[i] = g_pkU1[t][0][i];
    if (tid < CC) { ub1s[tid] = ub1[t*CC + tid]; ub2s[tid] = ub2[t*CC + tid]; }
    __syncthreads();

    float acc[16][4];
    #pragma unroll
    for (int nt = 0; nt < 16; nt++)
        acc[nt][0] = acc[nt][1] = acc[nt][2] = acc[nt][3] = 0.f;
    wgemm(acc, au, wbuf, mrow0, g, q, lid);
    __syncthreads();

    for (int r = wid; r < 256; r += 16) {
        const float4* a = (const float4*)(src + (size_t)(p0 + r) * CC);
        *(float4*)&au[r * ES + lid * 4] = f2tf4(a[lid]);
    }
    for (int i = tid; i < 4096; i += 512) wbuf[i] = g_pkU1[t][1][i];
    __syncthreads();
    wgemm(acc, au, wbuf, mrow0, g, q, lid);

    {
        int r0 = mrow0 + g, r1 = r0 + 8;
        #pragma unroll
        for (int nt = 0; nt < 16; nt++) {
            int n = nt * 8 + q * 2;
            float b0 = ub1s[n], b1 = ub1s[n + 1];
            *(float2*)&au[r0 * ES + n] = make_float2(f2tf(fmaxf(acc[nt][0] + b0, 0.f)),
                                                     f2tf(fmaxf(acc[nt][1] + b1, 0.f)));
            *(float2*)&au[r1 * ES + n] = make_float2(f2tf(fmaxf(acc[nt][2] + b0, 0.f)),
                                                     f2tf(fmaxf(acc[nt][3] + b1, 0.f)));
        }
    }
    __syncthreads();

    for (int i = tid; i < 4096; i += 512) wbuf[i] = g_pkU2[t][i];
    __syncthreads();

    #pragma unroll
    for (int nt = 0; nt < 16; nt++)
        acc[nt][0] = acc[nt][1] = acc[nt][2] = acc[nt][3] = 0.f;
    wgemm(acc, au, wbuf, mrow0, g, q, lid);

    {
        int r0 = mrow0 + g, r1 = r0 + 8;
        const float* s0 = src + (size_t)(p0 + r0) * CC;
        const float* s1 = src + (size_t)(p0 + r1) * CC;
        float* d0 = dst + (size_t)(p0 + r0) * CC;
        float* d1 = dst + (size_t)(p0 + r1) * CC;
        float* t0 = g_featTF + (size_t)(p0 + r0) * CC;
        float* t1 = g_featTF + (size_t)(p0 + r1) * CC;
        #pragma unroll
        for (int nt = 0; nt < 16; nt++) {
            int n = nt * 8 + q * 2;
            float b0 = ub2s[n], b1 = ub2s[n + 1];
            float2 x0 = *(const float2*)&s0[n];
            float2 x1 = *(const float2*)&s1[n];
            float2 v0 = make_float2(acc[nt][0] + b0 + x0.x, acc[nt][1] + b1 + x0.y);
            float2 v1 = make_float2(acc[nt][2] + b0 + x1.x, acc[nt][3] + b1 + x1.y);
            *(float2*)&d0[n] = v0;
            *(float2*)&d1[n] = v1;
            *(float2*)&t0[n] = make_float2(f2tf(v0.x), f2tf(v0.y));
            *(float2*)&t1[n] = make_float2(f2tf(v1.x), f2tf(v1.y));
        }
    }
}

// ---------------- launch ----------------
extern "C" void kernel_launch(void* const* d_in, const int* in_sizes, int n_in,
                              void* d_out, int out_size) {
    const float* xyz      = (const float*)d_in[0];
    const float* features = (const float*)d_in[1];
    const int*   knn      = (const int*)  d_in[2];
    const float* off_W1   = (const float*)d_in[3];
    const float* off_b1   = (const float*)d_in[4];
    const float* off_W2   = (const float*)d_in[5];
    const float* off_b2   = (const float*)d_in[6];
    const float* edge_W1  = (const float*)d_in[7];
    const float* edge_b1  = (const float*)d_in[8];
    const float* edge_W2  = (const float*)d_in[9];
    const float* edge_b2  = (const float*)d_in[10];
    const float* upd_W1   = (const float*)d_in[11];
    const float* upd_b1   = (const float*)d_in[12];
    const float* upd_W2   = (const float*)d_in[13];
    const float* upd_b2   = (const float*)d_in[14];
    float* out = (float*)d_out;

    float *featA, *featB;
    cudaGetSymbolAddress((void**)&featA, g_featA);
    cudaGetSymbolAddress((void**)&featB, g_featB);

    cudaFuncSetAttribute(offset_kernel, cudaFuncAttributeMaxDynamicSharedMemorySize, O_SMEM);
    cudaFuncSetAttribute(edge_kernel,   cudaFuncAttributeMaxDynamicSharedMemorySize, E_SMEM);
    cudaFuncSetAttribute(upd_kernel,    cudaFuncAttributeMaxDynamicSharedMemorySize, U_SMEM);
    int nsm = 148;
    cudaDeviceGetAttribute(&nsm, cudaDevAttrMultiProcessorCount, 0);

    prep_kernel<<<256, 256>>>(features, off_W1, off_W2, edge_W1, edge_b1, edge_W2,
                              upd_W1, upd_W2);

    const float* src = features;
    for (int t = 0; t < TT; t++) {
        float* dst = (t == TT-1) ? out : ((t == 0) ? featA : featB);
        offset_kernel<<<BN_/256, 512, O_SMEM>>>(src, xyz, off_b1, off_b2);
        edge_kernel<<<nsm, 512, E_SMEM>>>(xyz, knn, edge_b2, t);
        upd_kernel<<<BN_/256, 512, U_SMEM>>>(src, dst, upd_b1, upd_b2, t);
        src = dst;
    }
}

// round 17
// speedup vs baseline: 1.1494x; 1.0224x over previous
#include <cuda_runtime.h>
#include <cuda_bf16.h>
#include <cstdint>

#define BB 4
#define NN 8192
#define KK 16
#define CC 128
#define TT 3
#define BN_ (BB*NN)          // 32768 points
#define CE 131               // 3 + C
#define NTILES (BN_/8)       // 4096 edge tiles (8 points x 16 nbrs = 128 rows)
#define ES 132               // padded A row stride (floats) -> conflict-free frags

// ---------------- device scratch ----------------
__device__ __align__(16) float g_featA[BN_*CC];
__device__ __align__(16) float g_featB[BN_*CC];
__device__ __align__(16) float g_featTF[BN_*CC];  // tf32-rounded mirror of current features
__device__ __align__(16) float g_agg[BN_*CC];
__device__ float  g_center[BN_*3];
__device__ float4 g_posw[TT*CC];        // {w0,w1,w2,b1} per edge output n
// packed tf32 weight fragments: idx y in [0,4096): lid=y&31, nt=(y>>5)&15, p2=y>>9
// float4 = {W[n][16p2+q], W[n][16p2+q+4], W[n][16p2+q+8], W[n][16p2+q+12]}, n=nt*8+(lid>>2), q=lid&3
__device__ float4 g_pkE1[TT][4096];
__device__ float4 g_pkE2[TT][4096];
__device__ float4 g_pkU1[TT][2][4096];
__device__ float4 g_pkU2[TT][4096];
__device__ float4 g_pkO1[4096];
__device__ float4 g_pkO2[256];          // n8 fragment (rows 3..7 zero)

// ---------------- helpers ----------------
__device__ __forceinline__ float f2tf(float x) {
    uint32_t u; asm("cvt.rna.tf32.f32 %0, %1;" : "=r"(u) : "f"(x));
    return __uint_as_float(u);
}
__device__ __forceinline__ float4 f2tf4(float4 v) {
    v.x = f2tf(v.x); v.y = f2tf(v.y); v.z = f2tf(v.z); v.w = f2tf(v.w);
    return v;
}
__device__ __forceinline__ uint32_t s2u(const void* p) {
    uint32_t a;
    asm("{ .reg .u64 t; cvta.to.shared.u64 t, %1; cvt.u32.u64 %0, t; }" : "=r"(a) : "l"(p));
    return a;
}
__device__ __forceinline__ void cpasync16(uint32_t dst, const void* src) {
    asm volatile("cp.async.cg.shared.global [%0], [%1], 16;" :: "r"(dst), "l"(src));
}
#define CP_COMMIT() asm volatile("cp.async.commit_group;" ::: "memory")
#define CP_WAIT0()  asm volatile("cp.async.wait_group 0;" ::: "memory")

__device__ __forceinline__ void mma8(float* c, uint32_t a0, uint32_t a1,
                                     uint32_t a2, uint32_t a3,
                                     uint32_t b0, uint32_t b1) {
    asm volatile(
        "mma.sync.aligned.m16n8k8.row.col.f32.tf32.tf32.f32 "
        "{%0,%1,%2,%3}, {%4,%5,%6,%7}, {%8,%9}, {%0,%1,%2,%3};"
        : "+f"(c[0]), "+f"(c[1]), "+f"(c[2]), "+f"(c[3])
        : "r"(a0), "r"(a1), "r"(a2), "r"(a3), "r"(b0), "r"(b1));
}
__device__ __forceinline__ uint32_t ldu(const float* p) { return __float_as_uint(*p); }

// warp GEMM: 16 rows x 128 N over K=128, B fragments streamed from GLOBAL (L2-hot).
// Identical fragment math/order to the smem-B version -> bit-identical results.
__device__ __forceinline__ void wgemmG(float acc[16][4], const float* __restrict__ abase,
                                       const float4* __restrict__ pb,
                                       int mrow0, int g, int q, int lid) {
    const float* ar0 = abase + (mrow0 + g) * ES + q;
    const float* ar1 = ar0 + 8 * ES;
    #pragma unroll
    for (int p2 = 0; p2 < 8; p2++) {
        int k0 = p2 * 16;
        uint32_t aE0 = ldu(ar0 + k0),      aE2 = ldu(ar0 + k0 + 4);
        uint32_t aE1 = ldu(ar1 + k0),      aE3 = ldu(ar1 + k0 + 4);
        uint32_t aO0 = ldu(ar0 + k0 + 8),  aO2 = ldu(ar0 + k0 + 12);
        uint32_t aO1 = ldu(ar1 + k0 + 8),  aO3 = ldu(ar1 + k0 + 12);
        const float4* pbl = pb + p2 * 512 + lid;
        #pragma unroll
        for (int nt = 0; nt < 16; nt++) {
            float4 w = __ldg(&pbl[nt * 32]);
            mma8(acc[nt], aE0, aE1, aE2, aE3, __float_as_uint(w.x), __float_as_uint(w.y));
            mma8(acc[nt], aO0, aO1, aO2, aO3, __float_as_uint(w.z), __float_as_uint(w.w));
        }
    }
}

// edge warp GEMM: 32 rows (2x16 groups at row0) x 32 N (quarter nq) over K=128, B in smem.
__device__ __forceinline__ void wgemm32(float acc[2][4][4], const float* __restrict__ abase,
                                        const float4* __restrict__ pb,
                                        int row0, int g, int q, int lid, int nq) {
    const float* a0 = abase + (row0 + g) * ES + q;
    #pragma unroll
    for (int p2 = 0; p2 < 8; p2++) {
        int k0 = p2 * 16;
        uint32_t E0[2], E1[2], E2[2], E3[2], O0[2], O1[2], O2[2], O3[2];
        #pragma unroll
        for (int mg = 0; mg < 2; mg++) {
            const float* r0p = a0 + mg * 16 * ES + k0;
            const float* r1p = r0p + 8 * ES;
            E0[mg] = ldu(r0p);      E2[mg] = ldu(r0p + 4);
            E1[mg] = ldu(r1p);      E3[mg] = ldu(r1p + 4);
            O0[mg] = ldu(r0p + 8);  O2[mg] = ldu(r0p + 12);
            O1[mg] = ldu(r1p + 8);  O3[mg] = ldu(r1p + 12);
        }
        const float4* pbl = pb + p2 * 512 + nq * 128 + lid;
        #pragma unroll
        for (int ntl = 0; ntl < 4; ntl++) {
            float4 w = pbl[ntl * 32];
            uint32_t b0 = __float_as_uint(w.x), b1 = __float_as_uint(w.y);
            uint32_t b2 = __float_as_uint(w.z), b3 = __float_as_uint(w.w);
            #pragma unroll
            for (int mg = 0; mg < 2; mg++) {
                mma8(acc[mg][ntl], E0[mg], E1[mg], E2[mg], E3[mg], b0, b1);
                mma8(acc[mg][ntl], O0[mg], O1[mg], O2[mg], O3[mg], b2, b3);
            }
        }
    }
}

// ---------------- prep ----------------
__global__ void prep_kernel(const float* __restrict__ features,
                            const float* __restrict__ off_W1, const float* __restrict__ off_W2,
                            const float* __restrict__ edge_W1, const float* __restrict__ edge_b1,
                            const float* __restrict__ edge_W2,
                            const float* __restrict__ upd_W1, const float* __restrict__ upd_W2) {
    int i0 = blockIdx.x * blockDim.x + threadIdx.x, st = gridDim.x * blockDim.x;
    for (int x = i0; x < BN_ * CC; x += st) g_featTF[x] = f2tf(features[x]);
    for (int x = i0; x < TT * 4096; x += st) {
        int t = x >> 12, y = x & 4095;
        int lid = y & 31, nt = (y >> 5) & 15, p2 = y >> 9;
        int n = nt * 8 + (lid >> 2), q = lid & 3, k = p2 * 16 + q;
        const float* s1 = edge_W1 + ((size_t)t * CC + n) * CE + 3;
        g_pkE1[t][y] = make_float4(f2tf(s1[k]), f2tf(s1[k+4]), f2tf(s1[k+8]), f2tf(s1[k+12]));
        const float* s2 = edge_W2 + ((size_t)t * CC + n) * CC;
        g_pkE2[t][y] = make_float4(f2tf(s2[k]), f2tf(s2[k+4]), f2tf(s2[k+8]), f2tf(s2[k+12]));
        const float* u1 = upd_W1 + ((size_t)t * CC + n) * 2 * CC;
        g_pkU1[t][0][y] = make_float4(f2tf(u1[k]), f2tf(u1[k+4]), f2tf(u1[k+8]), f2tf(u1[k+12]));
        const float* u1b = u1 + CC;
        g_pkU1[t][1][y] = make_float4(f2tf(u1b[k]), f2tf(u1b[k+4]), f2tf(u1b[k+8]), f2tf(u1b[k+12]));
        const float* u2 = upd_W2 + ((size_t)t * CC + n) * CC;
        g_pkU2[t][y] = make_float4(f2tf(u2[k]), f2tf(u2[k+4]), f2tf(u2[k+8]), f2tf(u2[k+12]));
    }
    for (int x = i0; x < 4096; x += st) {
        int lid = x & 31, nt = (x >> 5) & 15, p2 = x >> 9;
        int n = nt * 8 + (lid >> 2), q = lid & 3, k = p2 * 16 + q;
        const float* s = off_W1 + (size_t)n * CC;
        g_pkO1[x] = make_float4(f2tf(s[k]), f2tf(s[k+4]), f2tf(s[k+8]), f2tf(s[k+12]));
    }
    for (int x = i0; x < 256; x += st) {
        int lid = x & 31, p2 = x >> 5;
        int n = lid >> 2, q = lid & 3, k = p2 * 16 + q;
        if (n < 3) {
            const float* s = off_W2 + (size_t)n * CC;
            g_pkO2[x] = make_float4(f2tf(s[k]), f2tf(s[k+4]), f2tf(s[k+8]), f2tf(s[k+12]));
        } else {
            g_pkO2[x] = make_float4(0.f, 0.f, 0.f, 0.f);
        }
    }
    for (int x = i0; x < TT * CC; x += st) {
        int t = x >> 7, n = x & 127;
        const float* w = edge_W1 + ((size_t)t * CC + n) * CE;
        g_posw[x] = make_float4(w[0], w[1], w[2], edge_b1[t * CC + n]);
    }
}

// ---------------- offset kernel: 256 threads, 128 points/CTA, 2 CTAs/SM ----------------
// smem floats: fs[128*ES]=16896, b1[128], b2[4]
#define O2_F    0
#define O2_B1   16896
#define O2_B2   17024
#define O2_SMEMF 17028
#define O2_SMEM  (O2_SMEMF*4)

__global__ void __launch_bounds__(256, 2) offset_kernel(
    const float* __restrict__ feat, const float* __restrict__ xyz,
    const float* __restrict__ b1, const float* __restrict__ b2) {
    extern __shared__ __align__(16) float sm[];
    float* fs  = sm + O2_F;
    float* b1s = sm + O2_B1;
    float* b2s = sm + O2_B2;

    const int tid = threadIdx.x, wid = tid >> 5, lid = tid & 31;
    const int g = lid >> 2, q = lid & 3;
    const int mrow0 = wid * 16;
    int p0 = blockIdx.x * 128;

    if (tid < CC) b1s[tid] = b1[tid];
    if (tid < 3)  b2s[tid] = b2[tid];
    for (int r = wid; r < 128; r += 8) {
        const float4* src = (const float4*)(feat + (size_t)(p0 + r) * CC);
        *(float4*)&fs[r * ES + lid * 4] = f2tf4(src[lid]);
    }
    __syncthreads();

    // layer 1 (B from L2)
    float acc[16][4];
    #pragma unroll
    for (int nt = 0; nt < 16; nt++)
        acc[nt][0] = acc[nt][1] = acc[nt][2] = acc[nt][3] = 0.f;
    wgemmG(acc, fs, g_pkO1, mrow0, g, q, lid);

    // epilogue: relu(+b1) -> own rows (warp-private; no sync needed)
    {
        int r0 = mrow0 + g, r1 = r0 + 8;
        #pragma unroll
        for (int nt = 0; nt < 16; nt++) {
            int n = nt * 8 + q * 2;
            float c0 = b1s[n], c1 = b1s[n + 1];
            *(float2*)&fs[r0 * ES + n] = make_float2(f2tf(fmaxf(acc[nt][0] + c0, 0.f)),
                                                     f2tf(fmaxf(acc[nt][1] + c1, 0.f)));
            *(float2*)&fs[r1 * ES + n] = make_float2(f2tf(fmaxf(acc[nt][2] + c0, 0.f)),
                                                     f2tf(fmaxf(acc[nt][3] + c1, 0.f)));
        }
    }

    // layer 2: N=3 (one zero-padded n8 fragment, from L2); reads own rows only
    float a2[4] = {0.f, 0.f, 0.f, 0.f};
    {
        const float* ar0 = fs + (mrow0 + g) * ES + q;
        const float* ar1 = ar0 + 8 * ES;
        #pragma unroll
        for (int p2 = 0; p2 < 8; p2++) {
            int k0 = p2 * 16;
            uint32_t aE0 = ldu(ar0 + k0),     aE2 = ldu(ar0 + k0 + 4);
            uint32_t aE1 = ldu(ar1 + k0),     aE3 = ldu(ar1 + k0 + 4);
            uint32_t aO0 = ldu(ar0 + k0 + 8), aO2 = ldu(ar0 + k0 + 12);
            uint32_t aO1 = ldu(ar1 + k0 + 8), aO3 = ldu(ar1 + k0 + 12);
            float4 w = __ldg(&g_pkO2[p2 * 32 + lid]);
            mma8(a2, aE0, aE1, aE2, aE3, __float_as_uint(w.x), __float_as_uint(w.y));
            mma8(a2, aO0, aO1, aO2, aO3, __float_as_uint(w.z), __float_as_uint(w.w));
        }
    }
    {
        int r0 = p0 + mrow0 + g, r1 = r0 + 8;
        if (q == 0) {
            g_center[r0*3 + 0] = xyz[r0*3 + 0] + a2[0] + b2s[0];
            g_center[r0*3 + 1] = xyz[r0*3 + 1] + a2[1] + b2s[1];
            g_center[r1*3 + 0] = xyz[r1*3 + 0] + a2[2] + b2s[0];
            g_center[r1*3 + 1] = xyz[r1*3 + 1] + a2[3] + b2s[1];
        } else if (q == 1) {
            g_center[r0*3 + 2] = xyz[r0*3 + 2] + a2[0] + b2s[2];
            g_center[r1*3 + 2] = xyz[r1*3 + 2] + a2[2] + b2s[2];
        }
    }
}

// ---------------- edge kernel: verbatim round-10 (best measured) ----------------
// smem floats: es[128*ES]=16896, w1 16384, w2 16384, relpos f4[128]=512, posw 512, eb2 128
#define EO_ES   0
#define EO_W1   16896
#define EO_W2   33280
#define EO_RP   49664
#define EO_PW   50176
#define EO_EB2  50688
#define E_SMEMF 50816
#define E_SMEM  (E_SMEMF*4)

__global__ void __launch_bounds__(512, 1) edge_kernel(
    const float* __restrict__ xyz, const int* __restrict__ knn,
    const float* __restrict__ eb2, int t) {
    extern __shared__ __align__(16) float sm[];
    float*  es   = sm + EO_ES;
    float4* w1s  = (float4*)(sm + EO_W1);
    float4* w2s  = (float4*)(sm + EO_W2);
    float4* relpos = (float4*)(sm + EO_RP);
    float4* posw   = (float4*)(sm + EO_PW);
    float*  eb2s   = sm + EO_EB2;

    const int tid = threadIdx.x, wid = tid >> 5, lid = tid & 31;
    const int g = lid >> 2, q = lid & 3;
    const int rw2 = wid & 3;         // row group of 32 (= 2 points)
    const int nq  = wid >> 2;        // N quarter
    const int row0 = rw2 * 32;
    const int grow = tid >> 2;       // gather row (0..127)
    const int seg  = tid & 3;        // 128B segment within row
    const uint32_t es_dst = s2u(es) + (uint32_t)(grow * ES + seg * 32) * 4;

    for (int i = tid; i < 4096; i += 512) { w1s[i] = g_pkE1[t][i]; w2s[i] = g_pkE2[t][i]; }
    if (tid < CC) { posw[tid] = g_posw[t * CC + tid]; eb2s[tid] = eb2[t * CC + tid]; }

    for (int tt = blockIdx.x; tt < NTILES; tt += gridDim.x) {
        int p0 = tt * 8;
        int base = p0 & ~(NN - 1);
        __syncthreads();   // previous tile's compute (and first-tile weight fill) complete

        // gather via cp.async from pre-rounded features
        {
            int idx = __ldg(&knn[(size_t)p0 * KK + grow]);
            const float* src = g_featTF + (size_t)(base + idx) * CC + seg * 32;
            #pragma unroll
            for (int j = 0; j < 8; j++)
                cpasync16(es_dst + j * 16, src + j * 4);
            CP_COMMIT();
        }
        if (tid < 128) {
            int r = tid, p = p0 + (r >> 4);
            int nb = base + __ldg(&knn[(size_t)p0 * KK + r]);
            float cx = g_center[p*3+0], cy = g_center[p*3+1], cz = g_center[p*3+2];
            relpos[r] = make_float4(xyz[nb*3+0]-cx, xyz[nb*3+1]-cy, xyz[nb*3+2]-cz, 0.f);
        }
        CP_WAIT0();
        __syncthreads();

        // layer 1 (feat part)
        float acc[2][4][4];
        #pragma unroll
        for (int mg = 0; mg < 2; mg++)
            #pragma unroll
            for (int ntl = 0; ntl < 4; ntl++)
                acc[mg][ntl][0] = acc[mg][ntl][1] = acc[mg][ntl][2] = acc[mg][ntl][3] = 0.f;
        wgemm32(acc, es, w1s, row0, g, q, lid, nq);

        // epilogue1: + rel_pos·W + b1 (exact fp32), ReLU, tf32 -> own rows/cols
        #pragma unroll
        for (int mg = 0; mg < 2; mg++) {
            int r0 = row0 + mg * 16 + g, r1 = r0 + 8;
            float4 rp0 = relpos[r0], rp1 = relpos[r1];
            #pragma unroll
            for (int ntl = 0; ntl < 4; ntl++) {
                int n = nq * 32 + ntl * 8 + q * 2;
                float4 pwa = posw[n], pwb = posw[n + 1];
                float pa0 = rp0.x*pwa.x + rp0.y*pwa.y + rp0.z*pwa.z + pwa.w;
                float pb0 = rp0.x*pwb.x + rp0.y*pwb.y + rp0.z*pwb.z + pwb.w;
                float pa1 = rp1.x*pwa.x + rp1.y*pwa.y + rp1.z*pwa.z + pwa.w;
                float pb1 = rp1.x*pwb.x + rp1.y*pwb.y + rp1.z*pwb.z + pwb.w;
                *(float2*)&es[r0 * ES + n] = make_float2(f2tf(fmaxf(acc[mg][ntl][0] + pa0, 0.f)),
                                                         f2tf(fmaxf(acc[mg][ntl][1] + pb0, 0.f)));
                *(float2*)&es[r1 * ES + n] = make_float2(f2tf(fmaxf(acc[mg][ntl][2] + pa1, 0.f)),
                                                         f2tf(fmaxf(acc[mg][ntl][3] + pb1, 0.f)));
            }
        }
        __syncthreads();

        // layer 2
        #pragma unroll
        for (int mg = 0; mg < 2; mg++)
            #pragma unroll
            for (int ntl = 0; ntl < 4; ntl++)
                acc[mg][ntl][0] = acc[mg][ntl][1] = acc[mg][ntl][2] = acc[mg][ntl][3] = 0.f;
        wgemm32(acc, es, w2s, row0, g, q, lid, nq);

        // epilogue2: per mg-group = one point's 16 neighbor rows -> max, +b2
        #pragma unroll
        for (int mg = 0; mg < 2; mg++) {
            int p = p0 + rw2 * 2 + mg;
            float* outp = g_agg + (size_t)p * CC;
            #pragma unroll
            for (int ntl = 0; ntl < 4; ntl++) {
                float m0 = fmaxf(acc[mg][ntl][0], acc[mg][ntl][2]);
                float m1 = fmaxf(acc[mg][ntl][1], acc[mg][ntl][3]);
                #pragma unroll
                for (int s = 4; s <= 16; s <<= 1) {
                    m0 = fmaxf(m0, __shfl_xor_sync(0xffffffffu, m0, s));
                    m1 = fmaxf(m1, __shfl_xor_sync(0xffffffffu, m1, s));
                }
                if (g == 0) {
                    int n = nq * 32 + ntl * 8 + q * 2;
                    *(float2*)&outp[n] = make_float2(m0 + eb2s[n], m1 + eb2s[n + 1]);
                }
            }
        }
    }
}

// ---------------- upd kernel: 256 threads, 128 points/CTA, 2 CTAs/SM ----------------
// smem floats: au[128*ES]=16896, ub1[128], ub2[128]
#define U2_A    0
#define U2_B1   16896
#define U2_B2   17024
#define U2_SMEMF 17152
#define U2_SMEM  (U2_SMEMF*4)

__global__ void __launch_bounds__(256, 2) upd_kernel(
    const float* __restrict__ src, float* __restrict__ dst,
    const float* __restrict__ ub1, const float* __restrict__ ub2, int t) {
    extern __shared__ __align__(16) float sm[];
    float* au   = sm + U2_A;
    float* ub1s = sm + U2_B1;
    float* ub2s = sm + U2_B2;

    const int tid = threadIdx.x, wid = tid >> 5, lid = tid & 31;
    const int g = lid >> 2, q = lid & 3;
    const int mrow0 = wid * 16;
    int p0 = blockIdx.x * 128;

    // A = agg
    for (int r = wid; r < 128; r += 8) {
        const float4* a = (const float4*)(g_agg + (size_t)(p0 + r) * CC);
        *(float4*)&au[r * ES + lid * 4] = f2tf4(a[lid]);
    }
    if (tid < CC) { ub1s[tid] = ub1[t*CC + tid]; ub2s[tid] = ub2[t*CC + tid]; }
    __syncthreads();

    // layer 1a: K = agg half (B from L2)
    float acc[16][4];
    #pragma unroll
    for (int nt = 0; nt < 16; nt++)
        acc[nt][0] = acc[nt][1] = acc[nt][2] = acc[nt][3] = 0.f;
    wgemmG(acc, au, g_pkU1[t][0], mrow0, g, q, lid);
    __syncthreads();   // all warps done reading au

    // A = feat
    for (int r = wid; r < 128; r += 8) {
        const float4* a = (const float4*)(src + (size_t)(p0 + r) * CC);
        *(float4*)&au[r * ES + lid * 4] = f2tf4(a[lid]);
    }
    __syncthreads();

    // layer 1b: K = feat half, accumulate
    wgemmG(acc, au, g_pkU1[t][1], mrow0, g, q, lid);

    // epilogue1: relu(acc + ub1) -> OWN rows (warp-private; layer-2 reads only own rows)
    {
        int r0 = mrow0 + g, r1 = r0 + 8;
        #pragma unroll
        for (int nt = 0; nt < 16; nt++) {
            int n = nt * 8 + q * 2;
            float b0 = ub1s[n], b1 = ub1s[n + 1];
            *(float2*)&au[r0 * ES + n] = make_float2(f2tf(fmaxf(acc[nt][0] + b0, 0.f)),
                                                     f2tf(fmaxf(acc[nt][1] + b1, 0.f)));
            *(float2*)&au[r1 * ES + n] = make_float2(f2tf(fmaxf(acc[nt][2] + b0, 0.f)),
                                                     f2tf(fmaxf(acc[nt][3] + b1, 0.f)));
        }
    }

    // layer 2 (own rows only -> no sync needed)
    #pragma unroll
    for (int nt = 0; nt < 16; nt++)
        acc[nt][0] = acc[nt][1] = acc[nt][2] = acc[nt][3] = 0.f;
    wgemmG(acc, au, g_pkU2[t], mrow0, g, q, lid);

    // epilogue2: out = acc + ub2 + src (fp32 residual); maintain featTF mirror
    {
        int r0 = mrow0 + g, r1 = r0 + 8;
        const float* s0 = src + (size_t)(p0 + r0) * CC;
        const float* s1 = src + (size_t)(p0 + r1) * CC;
        float* d0 = dst + (size_t)(p0 + r0) * CC;
        float* d1 = dst + (size_t)(p0 + r1) * CC;
        float* t0 = g_featTF + (size_t)(p0 + r0) * CC;
        float* t1 = g_featTF + (size_t)(p0 + r1) * CC;
        #pragma unroll
        for (int nt = 0; nt < 16; nt++) {
            int n = nt * 8 + q * 2;
            float b0 = ub2s[n], b1 = ub2s[n + 1];
            float2 x0 = *(const float2*)&s0[n];
            float2 x1 = *(const float2*)&s1[n];
            float2 v0 = make_float2(acc[nt][0] + b0 + x0.x, acc[nt][1] + b1 + x0.y);
            float2 v1 = make_float2(acc[nt][2] + b0 + x1.x, acc[nt][3] + b1 + x1.y);
            *(float2*)&d0[n] = v0;
            *(float2*)&d1[n] = v1;
            *(float2*)&t0[n] = make_float2(f2tf(v0.x), f2tf(v0.y));
            *(float2*)&t1[n] = make_float2(f2tf(v1.x), f2tf(v1.y));
        }
    }
}

// ---------------- launch ----------------
extern "C" void kernel_launch(void* const* d_in, const int* in_sizes, int n_in,
                              void* d_out, int out_size) {
    const float* xyz      = (const float*)d_in[0];
    const float* features = (const float*)d_in[1];
    const int*   knn      = (const int*)  d_in[2];
    const float* off_W1   = (const float*)d_in[3];
    const float* off_b1   = (const float*)d_in[4];
    const float* off_W2   = (const float*)d_in[5];
    const float* off_b2   = (const float*)d_in[6];
    const float* edge_W1  = (const float*)d_in[7];
    const float* edge_b1  = (const float*)d_in[8];
    const float* edge_W2  = (const float*)d_in[9];
    const float* edge_b2  = (const float*)d_in[10];
    const float* upd_W1   = (const float*)d_in[11];
    const float* upd_b1   = (const float*)d_in[12];
    const float* upd_W2   = (const float*)d_in[13];
    const float* upd_b2   = (const float*)d_in[14];
    float* out = (float*)d_out;

    float *featA, *featB;
    cudaGetSymbolAddress((void**)&featA, g_featA);
    cudaGetSymbolAddress((void**)&featB, g_featB);

    cudaFuncSetAttribute(offset_kernel, cudaFuncAttributeMaxDynamicSharedMemorySize, O2_SMEM);
    cudaFuncSetAttribute(edge_kernel,   cudaFuncAttributeMaxDynamicSharedMemorySize, E_SMEM);
    cudaFuncSetAttribute(upd_kernel,    cudaFuncAttributeMaxDynamicSharedMemorySize, U2_SMEM);
    int nsm = 148;
    cudaDeviceGetAttribute(&nsm, cudaDevAttrMultiProcessorCount, 0);

    prep_kernel<<<256, 256>>>(features, off_W1, off_W2, edge_W1, edge_b1, edge_W2,
                              upd_W1, upd_W2);

    const float* src = features;
    for (int t = 0; t < TT; t++) {
        float* dst = (t == TT-1) ? out : ((t == 0) ? featA : featB);
        offset_kernel<<<BN_/128, 256, O2_SMEM>>>(src, xyz, off_b1, off_b2);
        edge_kernel<<<nsm, 512, E_SMEM>>>(xyz, knn, edge_b2, t);
        upd_kernel<<<BN_/128, 256, U2_SMEM>>>(src, dst, upd_b1, upd_b2, t);
        src = dst;
    }
}